// round 15
// baseline (speedup 1.0000x reference)
#include <cuda_runtime.h>
#include <cuda_bf16.h>
#include <math.h>
#include <stdint.h>

// Problem constants
#define S    2048
#define HID  4096
#define NH   64
#define HD   64
#define ROT  32
#define QKV3 12288   // 3*HID
#define EPS  1e-5f
#define KDIM 4096
#define BKB  32
#define KITERS (KDIM / BKB)      // 128
#define QSCALE (0.125f * 1.4426950408889634f)   // 1/sqrt(HD) * log2(e)

// ---------------- scratch (device globals) ----------------
__device__ float g_cos[S * 16];
__device__ float g_sin[S * 16];
__device__ __nv_bfloat16 g_Ah[S * HID];
__device__ __nv_bfloat16 g_Al[S * HID];
__device__ __nv_bfloat16 g_Bqh[QKV3 * HID];
__device__ __nv_bfloat16 g_Bql[QKV3 * HID];
__device__ __nv_bfloat16 g_Bdh[HID * HID];
__device__ __nv_bfloat16 g_Bdl[HID * HID];
__device__ __nv_bfloat16 g_Qh[NH * S * HD];
__device__ __nv_bfloat16 g_Ql[NH * S * HD];
__device__ __nv_bfloat16 g_Kh[NH * S * HD];
__device__ __nv_bfloat16 g_Kl[NH * S * HD];
__device__ __nv_bfloat16 g_Vh[NH * S * HD];
__device__ __nv_bfloat16 g_Vl[NH * S * HD];

// ===================== PTX helpers =====================
__device__ __forceinline__ uint32_t smem_u32(const void* p) {
    uint32_t a;
    asm("{ .reg .u64 t; cvta.to.shared.u64 t, %1; cvt.u32.u64 %0, t; }" : "=r"(a) : "l"(p));
    return a;
}
__device__ __forceinline__ void cp16(uint32_t dst, const void* src) {
    asm volatile("cp.async.cg.shared.global [%0], [%1], 16;\n" :: "r"(dst), "l"(src));
}
__device__ __forceinline__ void cp_commit() { asm volatile("cp.async.commit_group;\n" ::: "memory"); }
__device__ __forceinline__ void cp_wait1()  { asm volatile("cp.async.wait_group 1;\n" ::: "memory"); }

__device__ __forceinline__ void ldsm4(uint32_t* r, uint32_t addr) {
    asm volatile("ldmatrix.sync.aligned.m8n8.x4.shared.b16 {%0,%1,%2,%3}, [%4];"
                 : "=r"(r[0]), "=r"(r[1]), "=r"(r[2]), "=r"(r[3]) : "r"(addr));
}
__device__ __forceinline__ void ldsm4t(uint32_t* r, uint32_t addr) {
    asm volatile("ldmatrix.sync.aligned.m8n8.x4.trans.shared.b16 {%0,%1,%2,%3}, [%4];"
                 : "=r"(r[0]), "=r"(r[1]), "=r"(r[2]), "=r"(r[3]) : "r"(addr));
}
__device__ __forceinline__ void mma16816(float* d, const uint32_t* a, const uint32_t* b) {
    asm volatile("mma.sync.aligned.m16n8k16.row.col.f32.bf16.bf16.f32 "
                 "{%0,%1,%2,%3}, {%4,%5,%6,%7}, {%8,%9}, {%0,%1,%2,%3};"
                 : "+f"(d[0]), "+f"(d[1]), "+f"(d[2]), "+f"(d[3])
                 : "r"(a[0]), "r"(a[1]), "r"(a[2]), "r"(a[3]), "r"(b[0]), "r"(b[1]));
}

__device__ __forceinline__ uint32_t swz64(int row, int kc) {
    return (uint32_t)(row * 64 + ((kc ^ ((row >> 1) & 3)) << 4));
}
__device__ __forceinline__ uint32_t swz128(int row, int c) {
    return (uint32_t)(row * 128 + ((c ^ (row & 7)) << 4));
}

// fast exp2 on fma/alu pipes; rel err ~2.4e-6
__device__ __forceinline__ float fexp2(float x) {
    x = fmaxf(x, -126.0f);
    float t = x + 12582912.0f;
    int   n = __float_as_int(t) - 0x4B400000;
    float f = x - (t - 12582912.0f);
    float p =      1.3333558146e-3f;
    p = fmaf(p, f, 9.6181291076e-3f);
    p = fmaf(p, f, 5.5504108665e-2f);
    p = fmaf(p, f, 2.4022650696e-1f);
    p = fmaf(p, f, 6.9314718056e-1f);
    p = fmaf(p, f, 1.0f);
    return __int_as_float(__float_as_int(p) + (n << 23));
}

// ===================== RoPE cos/sin table (exact reference numerics) =======
__global__ void rope_init(float* __restrict__ cosT, float* __restrict__ sinT)
{
    int idx = blockIdx.x * blockDim.x + threadIdx.x;
    if (idx >= S * 16) return;
    int s = idx >> 4, f = idx & 15;
    float invf = (float)pow(25000.0, -(double)f / 16.0);
    float ph = (float)s * invf;
    cosT[idx] = cosf(ph);
    sinT[idx] = sinf(ph);
}

// ===================== split / transpose conversion kernels ================
// Each thread handles 4 float4s (MLP=4).
__global__ void split_rows(const float* __restrict__ in, __nv_bfloat16* __restrict__ hi,
                           __nv_bfloat16* __restrict__ lo, int n4)
{
    int i0 = (blockIdx.x * blockDim.x + threadIdx.x) * 4;
    if (i0 >= n4) return;
    float4 v[4];
    #pragma unroll
    for (int u = 0; u < 4; u++) v[u] = ((const float4*)in)[i0 + u];
    #pragma unroll
    for (int u = 0; u < 4; u++) {
        int i = i0 + u;
        __nv_bfloat16 h0 = __float2bfloat16(v[u].x);
        __nv_bfloat16 h1 = __float2bfloat16(v[u].y);
        __nv_bfloat16 h2 = __float2bfloat16(v[u].z);
        __nv_bfloat16 h3 = __float2bfloat16(v[u].w);
        __nv_bfloat162 hA(h0, h1), hB(h2, h3);
        __nv_bfloat162 lA(__float2bfloat16(v[u].x - __bfloat162float(h0)),
                          __float2bfloat16(v[u].y - __bfloat162float(h1)));
        __nv_bfloat162 lB(__float2bfloat16(v[u].z - __bfloat162float(h2)),
                          __float2bfloat16(v[u].w - __bfloat162float(h3)));
        ((__nv_bfloat162*)hi)[2 * i]     = hA;
        ((__nv_bfloat162*)hi)[2 * i + 1] = hB;
        ((__nv_bfloat162*)lo)[2 * i]     = lA;
        ((__nv_bfloat162*)lo)[2 * i + 1] = lB;
    }
}

// in [K, Norig] fp32 -> out [N', K] bf16 hi/lo. Each block: 32 n-cols x 128 k
// (4 sub-tiles). Load phase issues 16 independent LDGs/thread (MLP=16).
// permute!=0: output row n' <- orig col h*192 + part*64 + d.
__global__ void split_transpose(const float* __restrict__ in, __nv_bfloat16* __restrict__ hi,
                                __nv_bfloat16* __restrict__ lo, int K, int N, int permute)
{
    __shared__ float t[4][32][33];
    const int n0 = blockIdx.x * 32, k0 = blockIdx.y * 128;
    const int tx = threadIdx.x, ty = threadIdx.y;

    int src0;
    if (permute) {
        int part = n0 >> 12, w = n0 & 4095;
        src0 = (w >> 6) * 192 + part * 64 + (w & 63);
    } else {
        src0 = n0;
    }

    #pragma unroll
    for (int tt = 0; tt < 4; tt++)
        #pragma unroll
        for (int r = 0; r < 4; r++)
            t[tt][ty + r * 8][tx] =
                in[(size_t)(k0 + tt * 32 + ty + r * 8) * N + src0 + tx];
    __syncthreads();

    const int tid = ty * 32 + tx;
    #pragma unroll
    for (int half = 0; half < 2; half++) {
        int task = tid + half * 256;      // 0..511
        int tt = task >> 7;               // sub-tile
        int q  = task & 3;                // k-octet within sub-tile
        int nl = (task & 127) >> 2;       // 0..31
        float v[8];
        #pragma unroll
        for (int i = 0; i < 8; i++) v[i] = t[tt][q * 8 + i][nl];

        uint32_t hw[4], lw[4];
        #pragma unroll
        for (int j = 0; j < 4; j++) {
            __nv_bfloat16 ha = __float2bfloat16(v[2 * j]);
            __nv_bfloat16 hb = __float2bfloat16(v[2 * j + 1]);
            __nv_bfloat162 hp(ha, hb);
            __nv_bfloat162 lp(__float2bfloat16(v[2 * j] - __bfloat162float(ha)),
                              __float2bfloat16(v[2 * j + 1] - __bfloat162float(hb)));
            hw[j] = *(uint32_t*)&hp;
            lw[j] = *(uint32_t*)&lp;
        }
        size_t o = (size_t)(n0 + nl) * K + k0 + tt * 32 + q * 8;
        *(uint4*)&hi[o] = make_uint4(hw[0], hw[1], hw[2], hw[3]);
        *(uint4*)&lo[o] = make_uint4(lw[0], lw[1], lw[2], lw[3]);
    }
}

// ===================== bf16x3 tensor-core GEMM =====================
// mode 0: C = A@B^T + bias (fp32 out).
// mode 1: QKV epilogue — B cols permuted part-major; fuse bias + per-head LN
//         + RoPE + bf16 hi/lo split; write Qh/Ql/Kh/Kl/Vh/Vl directly.
#define STG 32768
#define GEMM_SMEM (3 * STG)

__global__ __launch_bounds__(256, 2)
void gemm_bf16x3(const __nv_bfloat16* __restrict__ Ah, const __nv_bfloat16* __restrict__ Al,
                 const __nv_bfloat16* __restrict__ Bh, const __nv_bfloat16* __restrict__ Bl,
                 const float* __restrict__ bias, float* __restrict__ C, int N, int mode,
                 const float* __restrict__ qw, const float* __restrict__ qb,
                 const float* __restrict__ kw, const float* __restrict__ kb,
                 const float* __restrict__ cosT, const float* __restrict__ sinT,
                 __nv_bfloat16* __restrict__ Qh, __nv_bfloat16* __restrict__ Ql,
                 __nv_bfloat16* __restrict__ Kh, __nv_bfloat16* __restrict__ Kl,
                 __nv_bfloat16* __restrict__ Vh, __nv_bfloat16* __restrict__ Vl)
{
    extern __shared__ __align__(128) char smem[];
    const uint32_t sb = smem_u32(smem);
    const int tid = threadIdx.x, warp = tid >> 5, lane = tid & 31;
    const int wm = warp >> 1, wn = warp & 1;
    const int m0 = blockIdx.x * 128, n0 = blockIdx.y * 128;

    const char* srcs[4] = {
        (const char*)(Ah + (size_t)m0 * KDIM),
        (const char*)(Al + (size_t)m0 * KDIM),
        (const char*)(Bh + (size_t)n0 * KDIM),
        (const char*)(Bl + (size_t)n0 * KDIM)
    };

    const int ldrow0 = tid >> 2, ldc = tid & 3;
    const uint32_t dsw0 = swz64(ldrow0, ldc);
    const uint32_t dsw1 = swz64(ldrow0 + 64, ldc);

    auto load_stage = [&](int st, int kc) {
        uint32_t base = sb + st * STG;
        size_t kb = (size_t)kc * 64;
        #pragma unroll
        for (int mat = 0; mat < 4; mat++) {
            const char* s = srcs[mat];
            uint32_t d = base + mat * 8192;
            cp16(d + dsw0, s + (size_t)ldrow0 * 8192 + kb + ldc * 16);
            cp16(d + dsw1, s + (size_t)(ldrow0 + 64) * 8192 + kb + ldc * 16);
        }
    };

    const int g = lane >> 3, r = lane & 7;
    uint32_t offA[2][2], offB[4][2];
    #pragma unroll
    for (int mt = 0; mt < 2; mt++)
        #pragma unroll
        for (int ks = 0; ks < 2; ks++)
            offA[mt][ks] = swz64(wm * 32 + mt * 16 + (g & 1) * 8 + r, ks * 2 + (g >> 1));
    #pragma unroll
    for (int p = 0; p < 4; p++)
        #pragma unroll
        for (int ks = 0; ks < 2; ks++)
            offB[p][ks] = swz64(wn * 64 + p * 16 + (g >> 1) * 8 + r, ks * 2 + (g & 1));

    float acc[2][8][4];
    #pragma unroll
    for (int mt = 0; mt < 2; mt++)
        #pragma unroll
        for (int nt = 0; nt < 8; nt++)
            #pragma unroll
            for (int q = 0; q < 4; q++) acc[mt][nt][q] = 0.f;

    load_stage(0, 0); cp_commit();
    load_stage(1, 1); cp_commit();

    int st = 0;
    for (int i = 0; i < KITERS; i++) {
        cp_wait1();
        __syncthreads();
        int pst = st + 2; if (pst >= 3) pst -= 3;
        if (i + 2 < KITERS) load_stage(pst, i + 2);
        cp_commit();

        uint32_t base = sb + st * STG;
        #pragma unroll
        for (int ks = 0; ks < 2; ks++) {
            uint32_t ah[2][4], al[2][4], bh[8][2], bl[8][2];
            #pragma unroll
            for (int mt = 0; mt < 2; mt++) {
                ldsm4(ah[mt], base + offA[mt][ks]);
                ldsm4(al[mt], base + 8192 + offA[mt][ks]);
            }
            #pragma unroll
            for (int p = 0; p < 4; p++) {
                uint32_t t4[4];
                ldsm4(t4, base + 16384 + offB[p][ks]);
                bh[2*p][0] = t4[0]; bh[2*p][1] = t4[1];
                bh[2*p+1][0] = t4[2]; bh[2*p+1][1] = t4[3];
                ldsm4(t4, base + 24576 + offB[p][ks]);
                bl[2*p][0] = t4[0]; bl[2*p][1] = t4[1];
                bl[2*p+1][0] = t4[2]; bl[2*p+1][1] = t4[3];
            }
            #pragma unroll
            for (int mt = 0; mt < 2; mt++)
                #pragma unroll
                for (int nt = 0; nt < 8; nt++) {
                    mma16816(acc[mt][nt], ah[mt], bh[nt]);
                    mma16816(acc[mt][nt], ah[mt], bl[nt]);
                    mma16816(acc[mt][nt], al[mt], bh[nt]);
                }
        }
        st += 1; if (st >= 3) st -= 3;
    }

    if (mode == 0) {
        #pragma unroll
        for (int mt = 0; mt < 2; mt++) {
            int row0 = m0 + wm * 32 + mt * 16 + (lane >> 2);
            #pragma unroll
            for (int nt = 0; nt < 8; nt++) {
                int col = n0 + wn * 64 + nt * 8 + (lane & 3) * 2;
                float bx = __ldg(bias + col), by = __ldg(bias + col + 1);
                float2 v0 = make_float2(acc[mt][nt][0] + bx, acc[mt][nt][1] + by);
                float2 v1 = make_float2(acc[mt][nt][2] + bx, acc[mt][nt][3] + by);
                *(float2*)&C[(size_t)row0 * N + col] = v0;
                *(float2*)&C[(size_t)(row0 + 8) * N + col] = v1;
            }
        }
        return;
    }

    // ---- mode 1: fused QKV epilogue ----
    const int part  = blockIdx.y >> 5;                 // 0=Q, 1=K, 2=V
    const int hglob = ((n0 & 4095) >> 6) + wn;         // warp's head
    const int dbase = (lane & 3) * 2;

    float bcol[8][2], wln[8][2], bln[8][2];
    #pragma unroll
    for (int nt = 0; nt < 8; nt++)
        #pragma unroll
        for (int j = 0; j < 2; j++) {
            int d = nt * 8 + dbase + j;
            bcol[nt][j] = __ldg(bias + hglob * 192 + part * 64 + d);
            if (part < 2) {
                wln[nt][j] = __ldg((part == 0 ? qw : kw) + d);
                bln[nt][j] = __ldg((part == 0 ? qb : kb) + d);
            }
        }
    __nv_bfloat16* Oh_ = part == 0 ? Qh : (part == 1 ? Kh : Vh);
    __nv_bfloat16* Ol_ = part == 0 ? Ql : (part == 1 ? Kl : Vl);

    #pragma unroll
    for (int mt = 0; mt < 2; mt++)
        #pragma unroll
        for (int ri = 0; ri < 2; ri++) {
            int row = m0 + wm * 32 + mt * 16 + (lane >> 2) + ri * 8;
            float x[8][2];
            #pragma unroll
            for (int nt = 0; nt < 8; nt++) {
                x[nt][0] = acc[mt][nt][2 * ri + 0] + bcol[nt][0];
                x[nt][1] = acc[mt][nt][2 * ri + 1] + bcol[nt][1];
            }
            if (part < 2) {
                float sum = 0.f;
                #pragma unroll
                for (int nt = 0; nt < 8; nt++) sum += x[nt][0] + x[nt][1];
                sum += __shfl_xor_sync(0xffffffffu, sum, 1);
                sum += __shfl_xor_sync(0xffffffffu, sum, 2);
                float mu = sum * (1.f / 64.f);
                float vs = 0.f;
                #pragma unroll
                for (int nt = 0; nt < 8; nt++) {
                    float d0 = x[nt][0] - mu, d1 = x[nt][1] - mu;
                    vs += d0 * d0 + d1 * d1;
                }
                vs += __shfl_xor_sync(0xffffffffu, vs, 1);
                vs += __shfl_xor_sync(0xffffffffu, vs, 2);
                float rstd = rsqrtf(vs * (1.f / 64.f) + EPS);
                #pragma unroll
                for (int nt = 0; nt < 8; nt++) {
                    x[nt][0] = (x[nt][0] - mu) * rstd * wln[nt][0] + bln[nt][0];
                    x[nt][1] = (x[nt][1] - mu) * rstd * wln[nt][1] + bln[nt][1];
                }
                float c_[2][2], s_[2][2];
                #pragma unroll
                for (int a = 0; a < 2; a++)
                    #pragma unroll
                    for (int j = 0; j < 2; j++) {
                        int f = a * 8 + dbase + j;
                        c_[a][j] = __ldg(cosT + row * 16 + f);
                        s_[a][j] = __ldg(sinT + row * 16 + f);
                    }
                float yr[4][2];
                #pragma unroll
                for (int nt = 0; nt < 4; nt++)
                    #pragma unroll
                    for (int j = 0; j < 2; j++) {
                        float sign = nt < 2 ? -1.f : 1.f;
                        yr[nt][j] = x[nt][j] * c_[nt & 1][j] + sign * x[nt ^ 2][j] * s_[nt & 1][j];
                    }
                #pragma unroll
                for (int nt = 0; nt < 4; nt++) { x[nt][0] = yr[nt][0]; x[nt][1] = yr[nt][1]; }
                if (part == 0) {
                    #pragma unroll
                    for (int nt = 0; nt < 8; nt++) { x[nt][0] *= QSCALE; x[nt][1] *= QSCALE; }
                }
            }
            size_t ob = ((size_t)hglob * S + row) * 64 + dbase;
            #pragma unroll
            for (int nt = 0; nt < 8; nt++) {
                __nv_bfloat16 ha = __float2bfloat16(x[nt][0]);
                __nv_bfloat16 hb = __float2bfloat16(x[nt][1]);
                __nv_bfloat162 hp(ha, hb);
                __nv_bfloat162 lp(__float2bfloat16(x[nt][0] - __bfloat162float(ha)),
                                  __float2bfloat16(x[nt][1] - __bfloat162float(hb)));
                *(__nv_bfloat162*)&Oh_[ob + nt * 8] = hp;
                *(__nv_bfloat162*)&Ol_[ob + nt * 8] = lp;
            }
        }
}

// ---------------- flash attention: 128-q tile, 3-stage ring aliasing Q -----
#define ATT_STGSZ 32768
#define ATT_SMEM  (3 * ATT_STGSZ)

__global__ __launch_bounds__(256)
void flash_attn(const __nv_bfloat16* __restrict__ Qh, const __nv_bfloat16* __restrict__ Ql,
                const __nv_bfloat16* __restrict__ Kh, const __nv_bfloat16* __restrict__ Kl,
                const __nv_bfloat16* __restrict__ Vh, const __nv_bfloat16* __restrict__ Vl,
                __nv_bfloat16* __restrict__ Oh, __nv_bfloat16* __restrict__ Ol)
{
    extern __shared__ __align__(128) char smem[];
    const uint32_t sb = smem_u32(smem);
    const int h = blockIdx.y;
    const int t = gridDim.x - 1 - blockIdx.x;
    const int tid = threadIdx.x, warp = tid >> 5, lane = tid & 31;
    const int g = lane >> 3, r = lane & 7;

    const char* qhp = (const char*)(Qh + ((size_t)h * S + t * 128) * HD);
    const char* qlp = (const char*)(Ql + ((size_t)h * S + t * 128) * HD);
    const char* khp = (const char*)(Kh + (size_t)h * S * HD);
    const char* klp = (const char*)(Kl + (size_t)h * S * HD);
    const char* vhp = (const char*)(Vh + (size_t)h * S * HD);
    const char* vlp = (const char*)(Vl + (size_t)h * S * HD);

    const uint32_t regbase[3] = { sb + ATT_STGSZ, sb + 2 * ATT_STGSZ, sb };

    auto load_kv = [&](uint32_t base, int kt) {
        size_t gro = (size_t)kt * 64 * 128;
        for (int i = tid; i < 512; i += 256) {
            int row = i >> 3, c = i & 7;
            uint32_t o = swz128(row, c);
            size_t go = gro + row * 128 + c * 16;
            cp16(base + o,          khp + go);
            cp16(base + 8192 + o,   klp + go);
            cp16(base + 16384 + o,  vhp + go);
            cp16(base + 24576 + o,  vlp + go);
        }
    };

    const int kmax = 2 * t + 1;

    for (int i = tid; i < 1024; i += 256) {
        int row = i >> 3, c = i & 7;
        uint32_t o = swz128(row, c);
        cp16(sb + o, qhp + row * 128 + c * 16);
        cp16(sb + 16384 + o, qlp + row * 128 + c * 16);
    }
    load_kv(regbase[0], 0);
    cp_commit();
    load_kv(regbase[1], 1);
    cp_commit();

    uint32_t aQh[4][4], aQl[4][4];
    uint32_t offA[4];
    #pragma unroll
    for (int kc = 0; kc < 4; kc++)
        offA[kc] = swz128(warp * 16 + (g & 1) * 8 + r, kc * 2 + (g >> 1));

    float accO[8][4];
    #pragma unroll
    for (int nt = 0; nt < 8; nt++)
        #pragma unroll
        for (int c = 0; c < 4; c++) accO[nt][c] = 0.f;
    float m0 = -1e30f, m1 = -1e30f, l0 = 0.f, l1 = 0.f;

    const int qg0   = t * 128 + warp * 16 + (lane >> 2);
    const int qbase = t * 128 + warp * 16;
    const int qmax  = qbase + 15;

    int cur = 0;
    for (int kt = 0; kt <= kmax; kt++) {
        cp_wait1();
        __syncthreads();

        if (kt == 0) {
            #pragma unroll
            for (int kc = 0; kc < 4; kc++) {
                ldsm4(aQh[kc], sb + offA[kc]);
                ldsm4(aQl[kc], sb + 16384 + offA[kc]);
            }
            __syncthreads();
        }

        int pre = cur + 2; if (pre >= 3) pre -= 3;
        if (kt + 2 <= kmax) load_kv(regbase[pre], kt + 2);
        cp_commit();

        uint32_t base = regbase[cur];
        cur += 1; if (cur >= 3) cur -= 3;

        if (kt * 64 > qmax) continue;

        float s[8][4];
        #pragma unroll
        for (int nt = 0; nt < 8; nt++)
            #pragma unroll
            for (int c = 0; c < 4; c++) s[nt][c] = 0.f;
        #pragma unroll
        for (int kc = 0; kc < 4; kc++) {
            #pragma unroll
            for (int p = 0; p < 4; p++) {
                uint32_t offb = swz128(p * 16 + (g >> 1) * 8 + r, kc * 2 + (g & 1));
                uint32_t th[4], tl[4];
                ldsm4(th, base + offb);
                ldsm4(tl, base + 8192 + offb);
                mma16816(s[2*p],   aQh[kc], th);
                mma16816(s[2*p+1], aQh[kc], th + 2);
                mma16816(s[2*p],   aQh[kc], tl);
                mma16816(s[2*p+1], aQh[kc], tl + 2);
                mma16816(s[2*p],   aQl[kc], th);
                mma16816(s[2*p+1], aQl[kc], th + 2);
            }
        }

        if (kt * 64 + 63 > qbase) {
            #pragma unroll
            for (int nt = 0; nt < 8; nt++) {
                int kg = kt * 64 + nt * 8 + (lane & 3) * 2;
                if (kg > qg0)         s[nt][0] = -1e30f;
                if (kg + 1 > qg0)     s[nt][1] = -1e30f;
                if (kg > qg0 + 8)     s[nt][2] = -1e30f;
                if (kg + 1 > qg0 + 8) s[nt][3] = -1e30f;
            }
        }

        float mx0 = -1e30f, mx1 = -1e30f;
        #pragma unroll
        for (int nt = 0; nt < 8; nt++) {
            mx0 = fmaxf(mx0, fmaxf(s[nt][0], s[nt][1]));
            mx1 = fmaxf(mx1, fmaxf(s[nt][2], s[nt][3]));
        }
        mx0 = fmaxf(mx0, __shfl_xor_sync(0xffffffffu, mx0, 1));
        mx0 = fmaxf(mx0, __shfl_xor_sync(0xffffffffu, mx0, 2));
        mx1 = fmaxf(mx1, __shfl_xor_sync(0xffffffffu, mx1, 1));
        mx1 = fmaxf(mx1, __shfl_xor_sync(0xffffffffu, mx1, 2));
        float mn0 = fmaxf(m0, mx0), mn1 = fmaxf(m1, mx1);
        float corr0 = fexp2(m0 - mn0), corr1 = fexp2(m1 - mn1);
        m0 = mn0; m1 = mn1;
        l0 *= corr0; l1 *= corr1;
        #pragma unroll
        for (int nt = 0; nt < 8; nt++) {
            accO[nt][0] *= corr0; accO[nt][1] *= corr0;
            accO[nt][2] *= corr1; accO[nt][3] *= corr1;
        }

        uint32_t Ph0[8], Ph1[8], Pl0[8], Pl1[8];
        #pragma unroll
        for (int nt = 0; nt < 8; nt++) {
            float p0 = fexp2(s[nt][0] - m0);
            float p1 = fexp2(s[nt][1] - m0);
            float p2 = fexp2(s[nt][2] - m1);
            float p3 = fexp2(s[nt][3] - m1);
            l0 += p0 + p1; l1 += p2 + p3;
            __nv_bfloat162 h01 = __floats2bfloat162_rn(p0, p1);
            __nv_bfloat162 h23 = __floats2bfloat162_rn(p2, p3);
            __nv_bfloat162 q01 = __floats2bfloat162_rn(p0 - __low2float(h01), p1 - __high2float(h01));
            __nv_bfloat162 q23 = __floats2bfloat162_rn(p2 - __low2float(h23), p3 - __high2float(h23));
            Ph0[nt] = *(uint32_t*)&h01; Ph1[nt] = *(uint32_t*)&h23;
            Pl0[nt] = *(uint32_t*)&q01; Pl1[nt] = *(uint32_t*)&q23;
        }

        #pragma unroll
        for (int kc = 0; kc < 4; kc++) {
            uint32_t aPh[4] = {Ph0[2*kc], Ph1[2*kc], Ph0[2*kc+1], Ph1[2*kc+1]};
            uint32_t aPl[4] = {Pl0[2*kc], Pl1[2*kc], Pl0[2*kc+1], Pl1[2*kc+1]};
            #pragma unroll
            for (int p = 0; p < 4; p++) {
                uint32_t offv = swz128(kc * 16 + (g & 1) * 8 + r, p * 2 + (g >> 1));
                uint32_t vh[4], vl[4];
                ldsm4t(vh, base + 16384 + offv);
                ldsm4t(vl, base + 24576 + offv);
                mma16816(accO[2*p],   aPh, vh);
                mma16816(accO[2*p+1], aPh, vh + 2);
                mma16816(accO[2*p],   aPh, vl);
                mma16816(accO[2*p+1], aPh, vl + 2);
                mma16816(accO[2*p],   aPl, vh);
                mma16816(accO[2*p+1], aPl, vh + 2);
            }
        }
    }

    l0 += __shfl_xor_sync(0xffffffffu, l0, 1);
    l0 += __shfl_xor_sync(0xffffffffu, l0, 2);
    l1 += __shfl_xor_sync(0xffffffffu, l1, 1);
    l1 += __shfl_xor_sync(0xffffffffu, l1, 2);
    float inv0 = 1.f / l0, inv1 = 1.f / l1;
    int r0 = t * 128 + warp * 16 + (lane >> 2);
    #pragma unroll
    for (int nt = 0; nt < 8; nt++) {
        int col = h * 64 + nt * 8 + (lane & 3) * 2;
        float o0 = accO[nt][0] * inv0, o1 = accO[nt][1] * inv0;
        float o2 = accO[nt][2] * inv1, o3 = accO[nt][3] * inv1;
        __nv_bfloat162 h01 = __floats2bfloat162_rn(o0, o1);
        __nv_bfloat162 h23 = __floats2bfloat162_rn(o2, o3);
        __nv_bfloat162 q01 = __floats2bfloat162_rn(o0 - __low2float(h01), o1 - __high2float(h01));
        __nv_bfloat162 q23 = __floats2bfloat162_rn(o2 - __low2float(h23), o3 - __high2float(h23));
        *(__nv_bfloat162*)&Oh[(size_t)r0 * HID + col] = h01;
        *(__nv_bfloat162*)&Ol[(size_t)r0 * HID + col] = q01;
        *(__nv_bfloat162*)&Oh[(size_t)(r0 + 8) * HID + col] = h23;
        *(__nv_bfloat162*)&Ol[(size_t)(r0 + 8) * HID + col] = q23;
    }
}

// ---------------- launch ---------------------------------------------------
extern "C" void kernel_launch(void* const* d_in, const int* in_sizes, int n_in,
                              void* d_out, int out_size)
{
    const float* hs    = (const float*)d_in[0];
    const float* Wqkv  = (const float*)d_in[3];
    const float* bqkv  = (const float*)d_in[4];
    const float* Wd    = (const float*)d_in[5];
    const float* bd    = (const float*)d_in[6];
    const float* qw    = (const float*)d_in[7];
    const float* qb    = (const float*)d_in[8];
    const float* kw    = (const float*)d_in[9];
    const float* kb    = (const float*)d_in[10];
    float* out = (float*)d_out;

    float *cosT, *sinT;
    __nv_bfloat16 *Ahp, *Alp, *Bqh, *Bql, *Bdh, *Bdl;
    __nv_bfloat16 *Qhp, *Qlp, *Khp, *Klp, *Vhp, *Vlp;
    cudaGetSymbolAddress((void**)&cosT,  g_cos);
    cudaGetSymbolAddress((void**)&sinT,  g_sin);
    cudaGetSymbolAddress((void**)&Ahp,   g_Ah);
    cudaGetSymbolAddress((void**)&Alp,   g_Al);
    cudaGetSymbolAddress((void**)&Bqh,   g_Bqh);
    cudaGetSymbolAddress((void**)&Bql,   g_Bql);
    cudaGetSymbolAddress((void**)&Bdh,   g_Bdh);
    cudaGetSymbolAddress((void**)&Bdl,   g_Bdl);
    cudaGetSymbolAddress((void**)&Qhp,   g_Qh);
    cudaGetSymbolAddress((void**)&Qlp,   g_Ql);
    cudaGetSymbolAddress((void**)&Khp,   g_Kh);
    cudaGetSymbolAddress((void**)&Klp,   g_Kl);
    cudaGetSymbolAddress((void**)&Vhp,   g_Vh);
    cudaGetSymbolAddress((void**)&Vlp,   g_Vl);

    static int attr_set = 0;
    if (!attr_set) {
        cudaFuncSetAttribute(gemm_bf16x3, cudaFuncAttributeMaxDynamicSharedMemorySize, GEMM_SMEM);
        cudaFuncSetAttribute(flash_attn, cudaFuncAttributeMaxDynamicSharedMemorySize, ATT_SMEM);
        attr_set = 1;
    }

    rope_init<<<(S * 16 + 255) / 256, 256>>>(cosT, sinT);
    split_rows<<<(S * HID / 16 + 255) / 256, 256>>>(hs, Ahp, Alp, S * HID / 4);
    split_transpose<<<dim3(QKV3 / 32, HID / 128), dim3(32, 8)>>>(Wqkv, Bqh, Bql, KDIM, QKV3, 1);
    split_transpose<<<dim3(HID / 32, HID / 128), dim3(32, 8)>>>(Wd, Bdh, Bdl, KDIM, HID, 0);

    gemm_bf16x3<<<dim3(S / 128, QKV3 / 128), 256, GEMM_SMEM>>>(
        Ahp, Alp, Bqh, Bql, bqkv, nullptr, QKV3, 1,
        qw, qb, kw, kb, cosT, sinT, Qhp, Qlp, Khp, Klp, Vhp, Vlp);

    flash_attn<<<dim3(S / 128, NH), 256, ATT_SMEM>>>(Qhp, Qlp, Khp, Klp, Vhp, Vlp, Ahp, Alp);

    gemm_bf16x3<<<dim3(S / 128, HID / 128), 256, GEMM_SMEM>>>(
        Ahp, Alp, Bdh, Bdl, bd, out, HID, 0,
        nullptr, nullptr, nullptr, nullptr, nullptr, nullptr,
        nullptr, nullptr, nullptr, nullptr, nullptr, nullptr);
}

// round 16
// speedup vs baseline: 1.0093x; 1.0093x over previous
#include <cuda_runtime.h>
#include <cuda_bf16.h>
#include <math.h>
#include <stdint.h>

// Problem constants
#define S    2048
#define HID  4096
#define NH   64
#define HD   64
#define ROT  32
#define QKV3 12288   // 3*HID
#define EPS  1e-5f
#define KDIM 4096
#define BKB  32
#define KITERS (KDIM / BKB)      // 128
#define QSCALE (0.125f * 1.4426950408889634f)   // 1/sqrt(HD) * log2(e)

// ---------------- scratch (device globals) ----------------
__device__ float g_cos[S * 16];
__device__ float g_sin[S * 16];
__device__ __nv_bfloat16 g_Ah[S * HID];
__device__ __nv_bfloat16 g_Al[S * HID];
__device__ __nv_bfloat16 g_Bqh[QKV3 * HID];
__device__ __nv_bfloat16 g_Bql[QKV3 * HID];
__device__ __nv_bfloat16 g_Bdh[HID * HID];
__device__ __nv_bfloat16 g_Bdl[HID * HID];
__device__ __nv_bfloat16 g_Qh[NH * S * HD];
__device__ __nv_bfloat16 g_Ql[NH * S * HD];
__device__ __nv_bfloat16 g_Kh[NH * S * HD];
__device__ __nv_bfloat16 g_Kl[NH * S * HD];
__device__ __nv_bfloat16 g_Vh[NH * S * HD];
__device__ __nv_bfloat16 g_Vl[NH * S * HD];

// ===================== PTX helpers =====================
__device__ __forceinline__ uint32_t smem_u32(const void* p) {
    uint32_t a;
    asm("{ .reg .u64 t; cvta.to.shared.u64 t, %1; cvt.u32.u64 %0, t; }" : "=r"(a) : "l"(p));
    return a;
}
__device__ __forceinline__ void cp16(uint32_t dst, const void* src) {
    asm volatile("cp.async.cg.shared.global [%0], [%1], 16;\n" :: "r"(dst), "l"(src));
}
__device__ __forceinline__ void cp_commit() { asm volatile("cp.async.commit_group;\n" ::: "memory"); }
__device__ __forceinline__ void cp_wait1()  { asm volatile("cp.async.wait_group 1;\n" ::: "memory"); }

__device__ __forceinline__ void ldsm4(uint32_t* r, uint32_t addr) {
    asm volatile("ldmatrix.sync.aligned.m8n8.x4.shared.b16 {%0,%1,%2,%3}, [%4];"
                 : "=r"(r[0]), "=r"(r[1]), "=r"(r[2]), "=r"(r[3]) : "r"(addr));
}
__device__ __forceinline__ void ldsm4t(uint32_t* r, uint32_t addr) {
    asm volatile("ldmatrix.sync.aligned.m8n8.x4.trans.shared.b16 {%0,%1,%2,%3}, [%4];"
                 : "=r"(r[0]), "=r"(r[1]), "=r"(r[2]), "=r"(r[3]) : "r"(addr));
}
__device__ __forceinline__ void mma16816(float* d, const uint32_t* a, const uint32_t* b) {
    asm volatile("mma.sync.aligned.m16n8k16.row.col.f32.bf16.bf16.f32 "
                 "{%0,%1,%2,%3}, {%4,%5,%6,%7}, {%8,%9}, {%0,%1,%2,%3};"
                 : "+f"(d[0]), "+f"(d[1]), "+f"(d[2]), "+f"(d[3])
                 : "r"(a[0]), "r"(a[1]), "r"(a[2]), "r"(a[3]), "r"(b[0]), "r"(b[1]));
}

__device__ __forceinline__ uint32_t swz64(int row, int kc) {
    return (uint32_t)(row * 64 + ((kc ^ ((row >> 1) & 3)) << 4));
}
__device__ __forceinline__ uint32_t swz128(int row, int c) {
    return (uint32_t)(row * 128 + ((c ^ (row & 7)) << 4));
}

// fast exp2 on fma/alu pipes; rel err ~2.4e-6
__device__ __forceinline__ float fexp2(float x) {
    x = fmaxf(x, -126.0f);
    float t = x + 12582912.0f;
    int   n = __float_as_int(t) - 0x4B400000;
    float f = x - (t - 12582912.0f);
    float p =      1.3333558146e-3f;
    p = fmaf(p, f, 9.6181291076e-3f);
    p = fmaf(p, f, 5.5504108665e-2f);
    p = fmaf(p, f, 2.4022650696e-1f);
    p = fmaf(p, f, 6.9314718056e-1f);
    p = fmaf(p, f, 1.0f);
    return __int_as_float(__float_as_int(p) + (n << 23));
}

// ===================== RoPE cos/sin table (exact reference numerics) =======
__global__ void rope_init(float* __restrict__ cosT, float* __restrict__ sinT)
{
    int idx = blockIdx.x * blockDim.x + threadIdx.x;
    if (idx >= S * 16) return;
    int s = idx >> 4, f = idx & 15;
    float invf = (float)pow(25000.0, -(double)f / 16.0);
    float ph = (float)s * invf;
    cosT[idx] = cosf(ph);
    sinT[idx] = sinf(ph);
}

// ===================== split / transpose conversion kernels ================
// One float4 per thread (coalesced).
__global__ void split_rows(const float* __restrict__ in, __nv_bfloat16* __restrict__ hi,
                           __nv_bfloat16* __restrict__ lo, int n4)
{
    int i = blockIdx.x * blockDim.x + threadIdx.x;
    if (i >= n4) return;
    float4 v = ((const float4*)in)[i];
    __nv_bfloat16 h0 = __float2bfloat16(v.x);
    __nv_bfloat16 h1 = __float2bfloat16(v.y);
    __nv_bfloat16 h2 = __float2bfloat16(v.z);
    __nv_bfloat16 h3 = __float2bfloat16(v.w);
    __nv_bfloat16 l0 = __float2bfloat16(v.x - __bfloat162float(h0));
    __nv_bfloat16 l1 = __float2bfloat16(v.y - __bfloat162float(h1));
    __nv_bfloat16 l2 = __float2bfloat16(v.z - __bfloat162float(h2));
    __nv_bfloat16 l3 = __float2bfloat16(v.w - __bfloat162float(h3));
    ((__nv_bfloat162*)hi)[2 * i]     = __nv_bfloat162(h0, h1);
    ((__nv_bfloat162*)hi)[2 * i + 1] = __nv_bfloat162(h2, h3);
    ((__nv_bfloat162*)lo)[2 * i]     = __nv_bfloat162(l0, l1);
    ((__nv_bfloat162*)lo)[2 * i + 1] = __nv_bfloat162(l2, l3);
}

// in [K, Norig] fp32 -> out [N', K] bf16 hi/lo. Each block: 32 n-cols x 128 k
// (4 sub-tiles). Load phase issues 16 independent LDGs/thread (MLP=16).
// permute!=0: output row n' <- orig col h*192 + part*64 + d.
__global__ void split_transpose(const float* __restrict__ in, __nv_bfloat16* __restrict__ hi,
                                __nv_bfloat16* __restrict__ lo, int K, int N, int permute)
{
    __shared__ float t[4][32][33];
    const int n0 = blockIdx.x * 32, k0 = blockIdx.y * 128;
    const int tx = threadIdx.x, ty = threadIdx.y;

    int src0;
    if (permute) {
        int part = n0 >> 12, w = n0 & 4095;
        src0 = (w >> 6) * 192 + part * 64 + (w & 63);
    } else {
        src0 = n0;
    }

    #pragma unroll
    for (int tt = 0; tt < 4; tt++)
        #pragma unroll
        for (int r = 0; r < 4; r++)
            t[tt][ty + r * 8][tx] =
                in[(size_t)(k0 + tt * 32 + ty + r * 8) * N + src0 + tx];
    __syncthreads();

    const int tid = ty * 32 + tx;
    #pragma unroll
    for (int half = 0; half < 2; half++) {
        int task = tid + half * 256;      // 0..511
        int tt = task >> 7;               // sub-tile
        int q  = task & 3;                // k-octet within sub-tile
        int nl = (task & 127) >> 2;       // 0..31
        float v[8];
        #pragma unroll
        for (int i = 0; i < 8; i++) v[i] = t[tt][q * 8 + i][nl];

        uint32_t hw[4], lw[4];
        #pragma unroll
        for (int j = 0; j < 4; j++) {
            __nv_bfloat16 ha = __float2bfloat16(v[2 * j]);
            __nv_bfloat16 hb = __float2bfloat16(v[2 * j + 1]);
            __nv_bfloat162 hp(ha, hb);
            __nv_bfloat162 lp(__float2bfloat16(v[2 * j] - __bfloat162float(ha)),
                              __float2bfloat16(v[2 * j + 1] - __bfloat162float(hb)));
            hw[j] = *(uint32_t*)&hp;
            lw[j] = *(uint32_t*)&lp;
        }
        size_t o = (size_t)(n0 + nl) * K + k0 + tt * 32 + q * 8;
        *(uint4*)&hi[o] = make_uint4(hw[0], hw[1], hw[2], hw[3]);
        *(uint4*)&lo[o] = make_uint4(lw[0], lw[1], lw[2], lw[3]);
    }
}

// ===================== bf16x3 tensor-core GEMM =====================
// mode 0: C = A@B^T + bias (fp32 out).
// mode 1: QKV epilogue — B cols permuted part-major; fuse bias + per-head LN
//         + RoPE + bf16 hi/lo split; write Qh/Ql/Kh/Kl/Vh/Vl directly.
#define STG 32768
#define GEMM_SMEM (3 * STG)

__global__ __launch_bounds__(256, 2)
void gemm_bf16x3(const __nv_bfloat16* __restrict__ Ah, const __nv_bfloat16* __restrict__ Al,
                 const __nv_bfloat16* __restrict__ Bh, const __nv_bfloat16* __restrict__ Bl,
                 const float* __restrict__ bias, float* __restrict__ C, int N, int mode,
                 const float* __restrict__ qw, const float* __restrict__ qb,
                 const float* __restrict__ kw, const float* __restrict__ kb,
                 const float* __restrict__ cosT, const float* __restrict__ sinT,
                 __nv_bfloat16* __restrict__ Qh, __nv_bfloat16* __restrict__ Ql,
                 __nv_bfloat16* __restrict__ Kh, __nv_bfloat16* __restrict__ Kl,
                 __nv_bfloat16* __restrict__ Vh, __nv_bfloat16* __restrict__ Vl)
{
    extern __shared__ __align__(128) char smem[];
    const uint32_t sb = smem_u32(smem);
    const int tid = threadIdx.x, warp = tid >> 5, lane = tid & 31;
    const int wm = warp >> 1, wn = warp & 1;
    const int m0 = blockIdx.x * 128, n0 = blockIdx.y * 128;

    const char* srcs[4] = {
        (const char*)(Ah + (size_t)m0 * KDIM),
        (const char*)(Al + (size_t)m0 * KDIM),
        (const char*)(Bh + (size_t)n0 * KDIM),
        (const char*)(Bl + (size_t)n0 * KDIM)
    };

    const int ldrow0 = tid >> 2, ldc = tid & 3;
    const uint32_t dsw0 = swz64(ldrow0, ldc);
    const uint32_t dsw1 = swz64(ldrow0 + 64, ldc);

    auto load_stage = [&](int st, int kc) {
        uint32_t base = sb + st * STG;
        size_t kb = (size_t)kc * 64;
        #pragma unroll
        for (int mat = 0; mat < 4; mat++) {
            const char* s = srcs[mat];
            uint32_t d = base + mat * 8192;
            cp16(d + dsw0, s + (size_t)ldrow0 * 8192 + kb + ldc * 16);
            cp16(d + dsw1, s + (size_t)(ldrow0 + 64) * 8192 + kb + ldc * 16);
        }
    };

    const int g = lane >> 3, r = lane & 7;
    uint32_t offA[2][2], offB[4][2];
    #pragma unroll
    for (int mt = 0; mt < 2; mt++)
        #pragma unroll
        for (int ks = 0; ks < 2; ks++)
            offA[mt][ks] = swz64(wm * 32 + mt * 16 + (g & 1) * 8 + r, ks * 2 + (g >> 1));
    #pragma unroll
    for (int p = 0; p < 4; p++)
        #pragma unroll
        for (int ks = 0; ks < 2; ks++)
            offB[p][ks] = swz64(wn * 64 + p * 16 + (g >> 1) * 8 + r, ks * 2 + (g & 1));

    float acc[2][8][4];
    #pragma unroll
    for (int mt = 0; mt < 2; mt++)
        #pragma unroll
        for (int nt = 0; nt < 8; nt++)
            #pragma unroll
            for (int q = 0; q < 4; q++) acc[mt][nt][q] = 0.f;

    load_stage(0, 0); cp_commit();
    load_stage(1, 1); cp_commit();

    int st = 0;
    for (int i = 0; i < KITERS; i++) {
        cp_wait1();
        __syncthreads();
        int pst = st + 2; if (pst >= 3) pst -= 3;
        if (i + 2 < KITERS) load_stage(pst, i + 2);
        cp_commit();

        uint32_t base = sb + st * STG;
        #pragma unroll
        for (int ks = 0; ks < 2; ks++) {
            uint32_t ah[2][4], al[2][4], bh[8][2], bl[8][2];
            #pragma unroll
            for (int mt = 0; mt < 2; mt++) {
                ldsm4(ah[mt], base + offA[mt][ks]);
                ldsm4(al[mt], base + 8192 + offA[mt][ks]);
            }
            #pragma unroll
            for (int p = 0; p < 4; p++) {
                uint32_t t4[4];
                ldsm4(t4, base + 16384 + offB[p][ks]);
                bh[2*p][0] = t4[0]; bh[2*p][1] = t4[1];
                bh[2*p+1][0] = t4[2]; bh[2*p+1][1] = t4[3];
                ldsm4(t4, base + 24576 + offB[p][ks]);
                bl[2*p][0] = t4[0]; bl[2*p][1] = t4[1];
                bl[2*p+1][0] = t4[2]; bl[2*p+1][1] = t4[3];
            }
            #pragma unroll
            for (int mt = 0; mt < 2; mt++)
                #pragma unroll
                for (int nt = 0; nt < 8; nt++) {
                    mma16816(acc[mt][nt], ah[mt], bh[nt]);
                    mma16816(acc[mt][nt], ah[mt], bl[nt]);
                    mma16816(acc[mt][nt], al[mt], bh[nt]);
                }
        }
        st += 1; if (st >= 3) st -= 3;
    }

    if (mode == 0) {
        #pragma unroll
        for (int mt = 0; mt < 2; mt++) {
            int row0 = m0 + wm * 32 + mt * 16 + (lane >> 2);
            #pragma unroll
            for (int nt = 0; nt < 8; nt++) {
                int col = n0 + wn * 64 + nt * 8 + (lane & 3) * 2;
                float bx = __ldg(bias + col), by = __ldg(bias + col + 1);
                float2 v0 = make_float2(acc[mt][nt][0] + bx, acc[mt][nt][1] + by);
                float2 v1 = make_float2(acc[mt][nt][2] + bx, acc[mt][nt][3] + by);
                *(float2*)&C[(size_t)row0 * N + col] = v0;
                *(float2*)&C[(size_t)(row0 + 8) * N + col] = v1;
            }
        }
        return;
    }

    // ---- mode 1: fused QKV epilogue ----
    const int part  = blockIdx.y >> 5;                 // 0=Q, 1=K, 2=V
    const int hglob = ((n0 & 4095) >> 6) + wn;         // warp's head
    const int dbase = (lane & 3) * 2;

    float bcol[8][2], wln[8][2], bln[8][2];
    #pragma unroll
    for (int nt = 0; nt < 8; nt++)
        #pragma unroll
        for (int j = 0; j < 2; j++) {
            int d = nt * 8 + dbase + j;
            bcol[nt][j] = __ldg(bias + hglob * 192 + part * 64 + d);
            if (part < 2) {
                wln[nt][j] = __ldg((part == 0 ? qw : kw) + d);
                bln[nt][j] = __ldg((part == 0 ? qb : kb) + d);
            }
        }
    __nv_bfloat16* Oh_ = part == 0 ? Qh : (part == 1 ? Kh : Vh);
    __nv_bfloat16* Ol_ = part == 0 ? Ql : (part == 1 ? Kl : Vl);

    #pragma unroll
    for (int mt = 0; mt < 2; mt++)
        #pragma unroll
        for (int ri = 0; ri < 2; ri++) {
            int row = m0 + wm * 32 + mt * 16 + (lane >> 2) + ri * 8;
            float x[8][2];
            #pragma unroll
            for (int nt = 0; nt < 8; nt++) {
                x[nt][0] = acc[mt][nt][2 * ri + 0] + bcol[nt][0];
                x[nt][1] = acc[mt][nt][2 * ri + 1] + bcol[nt][1];
            }
            if (part < 2) {
                float sum = 0.f;
                #pragma unroll
                for (int nt = 0; nt < 8; nt++) sum += x[nt][0] + x[nt][1];
                sum += __shfl_xor_sync(0xffffffffu, sum, 1);
                sum += __shfl_xor_sync(0xffffffffu, sum, 2);
                float mu = sum * (1.f / 64.f);
                float vs = 0.f;
                #pragma unroll
                for (int nt = 0; nt < 8; nt++) {
                    float d0 = x[nt][0] - mu, d1 = x[nt][1] - mu;
                    vs += d0 * d0 + d1 * d1;
                }
                vs += __shfl_xor_sync(0xffffffffu, vs, 1);
                vs += __shfl_xor_sync(0xffffffffu, vs, 2);
                float rstd = rsqrtf(vs * (1.f / 64.f) + EPS);
                #pragma unroll
                for (int nt = 0; nt < 8; nt++) {
                    x[nt][0] = (x[nt][0] - mu) * rstd * wln[nt][0] + bln[nt][0];
                    x[nt][1] = (x[nt][1] - mu) * rstd * wln[nt][1] + bln[nt][1];
                }
                float c_[2][2], s_[2][2];
                #pragma unroll
                for (int a = 0; a < 2; a++)
                    #pragma unroll
                    for (int j = 0; j < 2; j++) {
                        int f = a * 8 + dbase + j;
                        c_[a][j] = __ldg(cosT + row * 16 + f);
                        s_[a][j] = __ldg(sinT + row * 16 + f);
                    }
                float yr[4][2];
                #pragma unroll
                for (int nt = 0; nt < 4; nt++)
                    #pragma unroll
                    for (int j = 0; j < 2; j++) {
                        float sign = nt < 2 ? -1.f : 1.f;
                        yr[nt][j] = x[nt][j] * c_[nt & 1][j] + sign * x[nt ^ 2][j] * s_[nt & 1][j];
                    }
                #pragma unroll
                for (int nt = 0; nt < 4; nt++) { x[nt][0] = yr[nt][0]; x[nt][1] = yr[nt][1]; }
                if (part == 0) {
                    #pragma unroll
                    for (int nt = 0; nt < 8; nt++) { x[nt][0] *= QSCALE; x[nt][1] *= QSCALE; }
                }
            }
            size_t ob = ((size_t)hglob * S + row) * 64 + dbase;
            #pragma unroll
            for (int nt = 0; nt < 8; nt++) {
                __nv_bfloat16 ha = __float2bfloat16(x[nt][0]);
                __nv_bfloat16 hb = __float2bfloat16(x[nt][1]);
                __nv_bfloat162 hp(ha, hb);
                __nv_bfloat162 lp(__float2bfloat16(x[nt][0] - __bfloat162float(ha)),
                                  __float2bfloat16(x[nt][1] - __bfloat162float(hb)));
                *(__nv_bfloat162*)&Oh_[ob + nt * 8] = hp;
                *(__nv_bfloat162*)&Ol_[ob + nt * 8] = lp;
            }
        }
}

// ---------------- flash attention: 128-q tile, 3-stage ring aliasing Q -----
#define ATT_STGSZ 32768
#define ATT_SMEM  (3 * ATT_STGSZ)

__global__ __launch_bounds__(256)
void flash_attn(const __nv_bfloat16* __restrict__ Qh, const __nv_bfloat16* __restrict__ Ql,
                const __nv_bfloat16* __restrict__ Kh, const __nv_bfloat16* __restrict__ Kl,
                const __nv_bfloat16* __restrict__ Vh, const __nv_bfloat16* __restrict__ Vl,
                __nv_bfloat16* __restrict__ Oh, __nv_bfloat16* __restrict__ Ol)
{
    extern __shared__ __align__(128) char smem[];
    const uint32_t sb = smem_u32(smem);
    const int h = blockIdx.y;
    const int t = gridDim.x - 1 - blockIdx.x;
    const int tid = threadIdx.x, warp = tid >> 5, lane = tid & 31;
    const int g = lane >> 3, r = lane & 7;

    const char* qhp = (const char*)(Qh + ((size_t)h * S + t * 128) * HD);
    const char* qlp = (const char*)(Ql + ((size_t)h * S + t * 128) * HD);
    const char* khp = (const char*)(Kh + (size_t)h * S * HD);
    const char* klp = (const char*)(Kl + (size_t)h * S * HD);
    const char* vhp = (const char*)(Vh + (size_t)h * S * HD);
    const char* vlp = (const char*)(Vl + (size_t)h * S * HD);

    const uint32_t regbase[3] = { sb + ATT_STGSZ, sb + 2 * ATT_STGSZ, sb };

    auto load_kv = [&](uint32_t base, int kt) {
        size_t gro = (size_t)kt * 64 * 128;
        for (int i = tid; i < 512; i += 256) {
            int row = i >> 3, c = i & 7;
            uint32_t o = swz128(row, c);
            size_t go = gro + row * 128 + c * 16;
            cp16(base + o,          khp + go);
            cp16(base + 8192 + o,   klp + go);
            cp16(base + 16384 + o,  vhp + go);
            cp16(base + 24576 + o,  vlp + go);
        }
    };

    const int kmax = 2 * t + 1;

    for (int i = tid; i < 1024; i += 256) {
        int row = i >> 3, c = i & 7;
        uint32_t o = swz128(row, c);
        cp16(sb + o, qhp + row * 128 + c * 16);
        cp16(sb + 16384 + o, qlp + row * 128 + c * 16);
    }
    load_kv(regbase[0], 0);
    cp_commit();
    load_kv(regbase[1], 1);
    cp_commit();

    uint32_t aQh[4][4], aQl[4][4];
    uint32_t offA[4];
    #pragma unroll
    for (int kc = 0; kc < 4; kc++)
        offA[kc] = swz128(warp * 16 + (g & 1) * 8 + r, kc * 2 + (g >> 1));

    float accO[8][4];
    #pragma unroll
    for (int nt = 0; nt < 8; nt++)
        #pragma unroll
        for (int c = 0; c < 4; c++) accO[nt][c] = 0.f;
    float m0 = -1e30f, m1 = -1e30f, l0 = 0.f, l1 = 0.f;

    const int qg0   = t * 128 + warp * 16 + (lane >> 2);
    const int qbase = t * 128 + warp * 16;
    const int qmax  = qbase + 15;

    int cur = 0;
    for (int kt = 0; kt <= kmax; kt++) {
        cp_wait1();
        __syncthreads();

        if (kt == 0) {
            #pragma unroll
            for (int kc = 0; kc < 4; kc++) {
                ldsm4(aQh[kc], sb + offA[kc]);
                ldsm4(aQl[kc], sb + 16384 + offA[kc]);
            }
            __syncthreads();
        }

        int pre = cur + 2; if (pre >= 3) pre -= 3;
        if (kt + 2 <= kmax) load_kv(regbase[pre], kt + 2);
        cp_commit();

        uint32_t base = regbase[cur];
        cur += 1; if (cur >= 3) cur -= 3;

        if (kt * 64 > qmax) continue;

        float s[8][4];
        #pragma unroll
        for (int nt = 0; nt < 8; nt++)
            #pragma unroll
            for (int c = 0; c < 4; c++) s[nt][c] = 0.f;
        #pragma unroll
        for (int kc = 0; kc < 4; kc++) {
            #pragma unroll
            for (int p = 0; p < 4; p++) {
                uint32_t offb = swz128(p * 16 + (g >> 1) * 8 + r, kc * 2 + (g & 1));
                uint32_t th[4], tl[4];
                ldsm4(th, base + offb);
                ldsm4(tl, base + 8192 + offb);
                mma16816(s[2*p],   aQh[kc], th);
                mma16816(s[2*p+1], aQh[kc], th + 2);
                mma16816(s[2*p],   aQh[kc], tl);
                mma16816(s[2*p+1], aQh[kc], tl + 2);
                mma16816(s[2*p],   aQl[kc], th);
                mma16816(s[2*p+1], aQl[kc], th + 2);
            }
        }

        if (kt * 64 + 63 > qbase) {
            #pragma unroll
            for (int nt = 0; nt < 8; nt++) {
                int kg = kt * 64 + nt * 8 + (lane & 3) * 2;
                if (kg > qg0)         s[nt][0] = -1e30f;
                if (kg + 1 > qg0)     s[nt][1] = -1e30f;
                if (kg > qg0 + 8)     s[nt][2] = -1e30f;
                if (kg + 1 > qg0 + 8) s[nt][3] = -1e30f;
            }
        }

        float mx0 = -1e30f, mx1 = -1e30f;
        #pragma unroll
        for (int nt = 0; nt < 8; nt++) {
            mx0 = fmaxf(mx0, fmaxf(s[nt][0], s[nt][1]));
            mx1 = fmaxf(mx1, fmaxf(s[nt][2], s[nt][3]));
        }
        mx0 = fmaxf(mx0, __shfl_xor_sync(0xffffffffu, mx0, 1));
        mx0 = fmaxf(mx0, __shfl_xor_sync(0xffffffffu, mx0, 2));
        mx1 = fmaxf(mx1, __shfl_xor_sync(0xffffffffu, mx1, 1));
        mx1 = fmaxf(mx1, __shfl_xor_sync(0xffffffffu, mx1, 2));
        float mn0 = fmaxf(m0, mx0), mn1 = fmaxf(m1, mx1);
        float corr0 = fexp2(m0 - mn0), corr1 = fexp2(m1 - mn1);
        m0 = mn0; m1 = mn1;
        l0 *= corr0; l1 *= corr1;
        #pragma unroll
        for (int nt = 0; nt < 8; nt++) {
            accO[nt][0] *= corr0; accO[nt][1] *= corr0;
            accO[nt][2] *= corr1; accO[nt][3] *= corr1;
        }

        uint32_t Ph0[8], Ph1[8], Pl0[8], Pl1[8];
        #pragma unroll
        for (int nt = 0; nt < 8; nt++) {
            float p0 = fexp2(s[nt][0] - m0);
            float p1 = fexp2(s[nt][1] - m0);
            float p2 = fexp2(s[nt][2] - m1);
            float p3 = fexp2(s[nt][3] - m1);
            l0 += p0 + p1; l1 += p2 + p3;
            __nv_bfloat162 h01 = __floats2bfloat162_rn(p0, p1);
            __nv_bfloat162 h23 = __floats2bfloat162_rn(p2, p3);
            __nv_bfloat162 q01 = __floats2bfloat162_rn(p0 - __low2float(h01), p1 - __high2float(h01));
            __nv_bfloat162 q23 = __floats2bfloat162_rn(p2 - __low2float(h23), p3 - __high2float(h23));
            Ph0[nt] = *(uint32_t*)&h01; Ph1[nt] = *(uint32_t*)&h23;
            Pl0[nt] = *(uint32_t*)&q01; Pl1[nt] = *(uint32_t*)&q23;
        }

        #pragma unroll
        for (int kc = 0; kc < 4; kc++) {
            uint32_t aPh[4] = {Ph0[2*kc], Ph1[2*kc], Ph0[2*kc+1], Ph1[2*kc+1]};
            uint32_t aPl[4] = {Pl0[2*kc], Pl1[2*kc], Pl0[2*kc+1], Pl1[2*kc+1]};
            #pragma unroll
            for (int p = 0; p < 4; p++) {
                uint32_t offv = swz128(kc * 16 + (g & 1) * 8 + r, p * 2 + (g >> 1));
                uint32_t vh[4], vl[4];
                ldsm4t(vh, base + 16384 + offv);
                ldsm4t(vl, base + 24576 + offv);
                mma16816(accO[2*p],   aPh, vh);
                mma16816(accO[2*p+1], aPh, vh + 2);
                mma16816(accO[2*p],   aPh, vl);
                mma16816(accO[2*p+1], aPh, vl + 2);
                mma16816(accO[2*p],   aPl, vh);
                mma16816(accO[2*p+1], aPl, vh + 2);
            }
        }
    }

    l0 += __shfl_xor_sync(0xffffffffu, l0, 1);
    l0 += __shfl_xor_sync(0xffffffffu, l0, 2);
    l1 += __shfl_xor_sync(0xffffffffu, l1, 1);
    l1 += __shfl_xor_sync(0xffffffffu, l1, 2);
    float inv0 = 1.f / l0, inv1 = 1.f / l1;
    int r0 = t * 128 + warp * 16 + (lane >> 2);
    #pragma unroll
    for (int nt = 0; nt < 8; nt++) {
        int col = h * 64 + nt * 8 + (lane & 3) * 2;
        float o0 = accO[nt][0] * inv0, o1 = accO[nt][1] * inv0;
        float o2 = accO[nt][2] * inv1, o3 = accO[nt][3] * inv1;
        __nv_bfloat162 h01 = __floats2bfloat162_rn(o0, o1);
        __nv_bfloat162 h23 = __floats2bfloat162_rn(o2, o3);
        __nv_bfloat162 q01 = __floats2bfloat162_rn(o0 - __low2float(h01), o1 - __high2float(h01));
        __nv_bfloat162 q23 = __floats2bfloat162_rn(o2 - __low2float(h23), o3 - __high2float(h23));
        *(__nv_bfloat162*)&Oh[(size_t)r0 * HID + col] = h01;
        *(__nv_bfloat162*)&Ol[(size_t)r0 * HID + col] = q01;
        *(__nv_bfloat162*)&Oh[(size_t)(r0 + 8) * HID + col] = h23;
        *(__nv_bfloat162*)&Ol[(size_t)(r0 + 8) * HID + col] = q23;
    }
}

// ---------------- launch ---------------------------------------------------
extern "C" void kernel_launch(void* const* d_in, const int* in_sizes, int n_in,
                              void* d_out, int out_size)
{
    const float* hs    = (const float*)d_in[0];
    const float* Wqkv  = (const float*)d_in[3];
    const float* bqkv  = (const float*)d_in[4];
    const float* Wd    = (const float*)d_in[5];
    const float* bd    = (const float*)d_in[6];
    const float* qw    = (const float*)d_in[7];
    const float* qb    = (const float*)d_in[8];
    const float* kw    = (const float*)d_in[9];
    const float* kb    = (const float*)d_in[10];
    float* out = (float*)d_out;

    float *cosT, *sinT;
    __nv_bfloat16 *Ahp, *Alp, *Bqh, *Bql, *Bdh, *Bdl;
    __nv_bfloat16 *Qhp, *Qlp, *Khp, *Klp, *Vhp, *Vlp;
    cudaGetSymbolAddress((void**)&cosT,  g_cos);
    cudaGetSymbolAddress((void**)&sinT,  g_sin);
    cudaGetSymbolAddress((void**)&Ahp,   g_Ah);
    cudaGetSymbolAddress((void**)&Alp,   g_Al);
    cudaGetSymbolAddress((void**)&Bqh,   g_Bqh);
    cudaGetSymbolAddress((void**)&Bql,   g_Bql);
    cudaGetSymbolAddress((void**)&Bdh,   g_Bdh);
    cudaGetSymbolAddress((void**)&Bdl,   g_Bdl);
    cudaGetSymbolAddress((void**)&Qhp,   g_Qh);
    cudaGetSymbolAddress((void**)&Qlp,   g_Ql);
    cudaGetSymbolAddress((void**)&Khp,   g_Kh);
    cudaGetSymbolAddress((void**)&Klp,   g_Kl);
    cudaGetSymbolAddress((void**)&Vhp,   g_Vh);
    cudaGetSymbolAddress((void**)&Vlp,   g_Vl);

    static int attr_set = 0;
    static cudaStream_t s1;
    static cudaEvent_t evFork, evJoin;
    if (!attr_set) {
        cudaFuncSetAttribute(gemm_bf16x3, cudaFuncAttributeMaxDynamicSharedMemorySize, GEMM_SMEM);
        cudaFuncSetAttribute(flash_attn, cudaFuncAttributeMaxDynamicSharedMemorySize, ATT_SMEM);
        cudaStreamCreate(&s1);
        cudaEventCreateWithFlags(&evFork, cudaEventDisableTiming);
        cudaEventCreateWithFlags(&evJoin, cudaEventDisableTiming);
        attr_set = 1;
    }

    // fork: dense-weight transpose runs on s1 concurrent with main chain
    cudaEventRecord(evFork, 0);
    cudaStreamWaitEvent(s1, evFork, 0);
    split_transpose<<<dim3(HID / 32, HID / 128), dim3(32, 8), 0, s1>>>(Wd, Bdh, Bdl, KDIM, HID, 0);
    cudaEventRecord(evJoin, s1);

    // main chain (legacy stream)
    rope_init<<<(S * 16 + 255) / 256, 256>>>(cosT, sinT);
    split_rows<<<(S * HID / 4 + 255) / 256, 256>>>(hs, Ahp, Alp, S * HID / 4);
    split_transpose<<<dim3(QKV3 / 32, HID / 128), dim3(32, 8)>>>(Wqkv, Bqh, Bql, KDIM, QKV3, 1);

    gemm_bf16x3<<<dim3(S / 128, QKV3 / 128), 256, GEMM_SMEM>>>(
        Ahp, Alp, Bqh, Bql, bqkv, nullptr, QKV3, 1,
        qw, qb, kw, kb, cosT, sinT, Qhp, Qlp, Khp, Klp, Vhp, Vlp);

    flash_attn<<<dim3(S / 128, NH), 256, ATT_SMEM>>>(Qhp, Qlp, Khp, Klp, Vhp, Vlp, Ahp, Alp);

    // join before dense GEMM consumes Bdh/Bdl
    cudaStreamWaitEvent(0, evJoin, 0);
    gemm_bf16x3<<<dim3(S / 128, HID / 128), 256, GEMM_SMEM>>>(
        Ahp, Alp, Bdh, Bdl, bd, out, HID, 0,
        nullptr, nullptr, nullptr, nullptr, nullptr, nullptr,
        nullptr, nullptr, nullptr, nullptr, nullptr, nullptr);
}

// round 17
// speedup vs baseline: 1.0109x; 1.0016x over previous
#include <cuda_runtime.h>
#include <cuda_bf16.h>
#include <math.h>
#include <stdint.h>

// Problem constants
#define S    2048
#define HID  4096
#define NH   64
#define HD   64
#define ROT  32
#define QKV3 12288   // 3*HID
#define EPS  1e-5f
#define KDIM 4096
#define BKB  32
#define KITERS (KDIM / BKB)      // 128
#define QSCALE (0.125f * 1.4426950408889634f)   // 1/sqrt(HD) * log2(e)

// ---------------- scratch (device globals) ----------------
__device__ float g_cos[S * 16];
__device__ float g_sin[S * 16];
__device__ __nv_bfloat16 g_Ah[S * HID];
__device__ __nv_bfloat16 g_Al[S * HID];
__device__ __nv_bfloat16 g_Bqh[QKV3 * HID];
__device__ __nv_bfloat16 g_Bql[QKV3 * HID];
__device__ __nv_bfloat16 g_Bdh[HID * HID];
__device__ __nv_bfloat16 g_Bdl[HID * HID];
__device__ __nv_bfloat16 g_Qh[NH * S * HD];
__device__ __nv_bfloat16 g_Ql[NH * S * HD];
__device__ __nv_bfloat16 g_Kh[NH * S * HD];
__device__ __nv_bfloat16 g_Kl[NH * S * HD];
__device__ __nv_bfloat16 g_Vh[NH * S * HD];
__device__ __nv_bfloat16 g_Vl[NH * S * HD];

// ===================== PTX helpers =====================
__device__ __forceinline__ uint32_t smem_u32(const void* p) {
    uint32_t a;
    asm("{ .reg .u64 t; cvta.to.shared.u64 t, %1; cvt.u32.u64 %0, t; }" : "=r"(a) : "l"(p));
    return a;
}
__device__ __forceinline__ void cp16(uint32_t dst, const void* src) {
    asm volatile("cp.async.cg.shared.global [%0], [%1], 16;\n" :: "r"(dst), "l"(src));
}
__device__ __forceinline__ void cp_commit() { asm volatile("cp.async.commit_group;\n" ::: "memory"); }
__device__ __forceinline__ void cp_wait1()  { asm volatile("cp.async.wait_group 1;\n" ::: "memory"); }

__device__ __forceinline__ void ldsm4(uint32_t* r, uint32_t addr) {
    asm volatile("ldmatrix.sync.aligned.m8n8.x4.shared.b16 {%0,%1,%2,%3}, [%4];"
                 : "=r"(r[0]), "=r"(r[1]), "=r"(r[2]), "=r"(r[3]) : "r"(addr));
}
__device__ __forceinline__ void ldsm4t(uint32_t* r, uint32_t addr) {
    asm volatile("ldmatrix.sync.aligned.m8n8.x4.trans.shared.b16 {%0,%1,%2,%3}, [%4];"
                 : "=r"(r[0]), "=r"(r[1]), "=r"(r[2]), "=r"(r[3]) : "r"(addr));
}
__device__ __forceinline__ void mma16816(float* d, const uint32_t* a, const uint32_t* b) {
    asm volatile("mma.sync.aligned.m16n8k16.row.col.f32.bf16.bf16.f32 "
                 "{%0,%1,%2,%3}, {%4,%5,%6,%7}, {%8,%9}, {%0,%1,%2,%3};"
                 : "+f"(d[0]), "+f"(d[1]), "+f"(d[2]), "+f"(d[3])
                 : "r"(a[0]), "r"(a[1]), "r"(a[2]), "r"(a[3]), "r"(b[0]), "r"(b[1]));
}

__device__ __forceinline__ uint32_t swz64(int row, int kc) {
    return (uint32_t)(row * 64 + ((kc ^ ((row >> 1) & 3)) << 4));
}
__device__ __forceinline__ uint32_t swz128(int row, int c) {
    return (uint32_t)(row * 128 + ((c ^ (row & 7)) << 4));
}

// fast exp2 on fma/alu pipes; rel err ~2.4e-6
__device__ __forceinline__ float fexp2(float x) {
    x = fmaxf(x, -126.0f);
    float t = x + 12582912.0f;
    int   n = __float_as_int(t) - 0x4B400000;
    float f = x - (t - 12582912.0f);
    float p =      1.3333558146e-3f;
    p = fmaf(p, f, 9.6181291076e-3f);
    p = fmaf(p, f, 5.5504108665e-2f);
    p = fmaf(p, f, 2.4022650696e-1f);
    p = fmaf(p, f, 6.9314718056e-1f);
    p = fmaf(p, f, 1.0f);
    return __int_as_float(__float_as_int(p) + (n << 23));
}

// ===================== RoPE cos/sin table (exact reference numerics) =======
__global__ void rope_init(float* __restrict__ cosT, float* __restrict__ sinT)
{
    int idx = blockIdx.x * blockDim.x + threadIdx.x;
    if (idx >= S * 16) return;
    int s = idx >> 4, f = idx & 15;
    float invf = (float)pow(25000.0, -(double)f / 16.0);
    float ph = (float)s * invf;
    cosT[idx] = cosf(ph);
    sinT[idx] = sinf(ph);
}

// ===================== split / transpose conversion kernels ================
// One float4 per thread (coalesced).
__global__ void split_rows(const float* __restrict__ in, __nv_bfloat16* __restrict__ hi,
                           __nv_bfloat16* __restrict__ lo, int n4)
{
    int i = blockIdx.x * blockDim.x + threadIdx.x;
    if (i >= n4) return;
    float4 v = ((const float4*)in)[i];
    __nv_bfloat16 h0 = __float2bfloat16(v.x);
    __nv_bfloat16 h1 = __float2bfloat16(v.y);
    __nv_bfloat16 h2 = __float2bfloat16(v.z);
    __nv_bfloat16 h3 = __float2bfloat16(v.w);
    __nv_bfloat16 l0 = __float2bfloat16(v.x - __bfloat162float(h0));
    __nv_bfloat16 l1 = __float2bfloat16(v.y - __bfloat162float(h1));
    __nv_bfloat16 l2 = __float2bfloat16(v.z - __bfloat162float(h2));
    __nv_bfloat16 l3 = __float2bfloat16(v.w - __bfloat162float(h3));
    ((__nv_bfloat162*)hi)[2 * i]     = __nv_bfloat162(h0, h1);
    ((__nv_bfloat162*)hi)[2 * i + 1] = __nv_bfloat162(h2, h3);
    ((__nv_bfloat162*)lo)[2 * i]     = __nv_bfloat162(l0, l1);
    ((__nv_bfloat162*)lo)[2 * i + 1] = __nv_bfloat162(l2, l3);
}

// in [K, Norig] fp32 -> out [N', K] bf16 hi/lo. Each block: 32 n-cols x 128 k
// (4 sub-tiles). Load phase issues 16 independent LDGs/thread (MLP=16).
// permute!=0: output row n' <- orig col h*192 + part*64 + d.
__global__ void split_transpose(const float* __restrict__ in, __nv_bfloat16* __restrict__ hi,
                                __nv_bfloat16* __restrict__ lo, int K, int N, int permute)
{
    __shared__ float t[4][32][33];
    const int n0 = blockIdx.x * 32, k0 = blockIdx.y * 128;
    const int tx = threadIdx.x, ty = threadIdx.y;

    int src0;
    if (permute) {
        int part = n0 >> 12, w = n0 & 4095;
        src0 = (w >> 6) * 192 + part * 64 + (w & 63);
    } else {
        src0 = n0;
    }

    #pragma unroll
    for (int tt = 0; tt < 4; tt++)
        #pragma unroll
        for (int r = 0; r < 4; r++)
            t[tt][ty + r * 8][tx] =
                in[(size_t)(k0 + tt * 32 + ty + r * 8) * N + src0 + tx];
    __syncthreads();

    const int tid = ty * 32 + tx;
    #pragma unroll
    for (int half = 0; half < 2; half++) {
        int task = tid + half * 256;      // 0..511
        int tt = task >> 7;               // sub-tile
        int q  = task & 3;                // k-octet within sub-tile
        int nl = (task & 127) >> 2;       // 0..31
        float v[8];
        #pragma unroll
        for (int i = 0; i < 8; i++) v[i] = t[tt][q * 8 + i][nl];

        uint32_t hw[4], lw[4];
        #pragma unroll
        for (int j = 0; j < 4; j++) {
            __nv_bfloat16 ha = __float2bfloat16(v[2 * j]);
            __nv_bfloat16 hb = __float2bfloat16(v[2 * j + 1]);
            __nv_bfloat162 hp(ha, hb);
            __nv_bfloat162 lp(__float2bfloat16(v[2 * j] - __bfloat162float(ha)),
                              __float2bfloat16(v[2 * j + 1] - __bfloat162float(hb)));
            hw[j] = *(uint32_t*)&hp;
            lw[j] = *(uint32_t*)&lp;
        }
        size_t o = (size_t)(n0 + nl) * K + k0 + tt * 32 + q * 8;
        *(uint4*)&hi[o] = make_uint4(hw[0], hw[1], hw[2], hw[3]);
        *(uint4*)&lo[o] = make_uint4(lw[0], lw[1], lw[2], lw[3]);
    }
}

// ===================== bf16x3 tensor-core GEMM =====================
// mode 0: C = A@B^T + bias (fp32 out).
// mode 1: QKV epilogue — B cols permuted part-major; fuse bias + per-head LN
//         + RoPE + bf16 hi/lo split; write Qh/Ql/Kh/Kl/Vh/Vl directly.
#define STG 32768
#define GEMM_SMEM (3 * STG)

__global__ __launch_bounds__(256, 2)
void gemm_bf16x3(const __nv_bfloat16* __restrict__ Ah, const __nv_bfloat16* __restrict__ Al,
                 const __nv_bfloat16* __restrict__ Bh, const __nv_bfloat16* __restrict__ Bl,
                 const float* __restrict__ bias, float* __restrict__ C, int N, int mode,
                 const float* __restrict__ qw, const float* __restrict__ qb,
                 const float* __restrict__ kw, const float* __restrict__ kb,
                 const float* __restrict__ cosT, const float* __restrict__ sinT,
                 __nv_bfloat16* __restrict__ Qh, __nv_bfloat16* __restrict__ Ql,
                 __nv_bfloat16* __restrict__ Kh, __nv_bfloat16* __restrict__ Kl,
                 __nv_bfloat16* __restrict__ Vh, __nv_bfloat16* __restrict__ Vl)
{
    extern __shared__ __align__(128) char smem[];
    const uint32_t sb = smem_u32(smem);
    const int tid = threadIdx.x, warp = tid >> 5, lane = tid & 31;
    const int wm = warp >> 1, wn = warp & 1;
    const int m0 = blockIdx.x * 128, n0 = blockIdx.y * 128;

    const char* srcs[4] = {
        (const char*)(Ah + (size_t)m0 * KDIM),
        (const char*)(Al + (size_t)m0 * KDIM),
        (const char*)(Bh + (size_t)n0 * KDIM),
        (const char*)(Bl + (size_t)n0 * KDIM)
    };

    const int ldrow0 = tid >> 2, ldc = tid & 3;
    const uint32_t dsw0 = swz64(ldrow0, ldc);
    const uint32_t dsw1 = swz64(ldrow0 + 64, ldc);

    auto load_stage = [&](int st, int kc) {
        uint32_t base = sb + st * STG;
        size_t kb = (size_t)kc * 64;
        #pragma unroll
        for (int mat = 0; mat < 4; mat++) {
            const char* s = srcs[mat];
            uint32_t d = base + mat * 8192;
            cp16(d + dsw0, s + (size_t)ldrow0 * 8192 + kb + ldc * 16);
            cp16(d + dsw1, s + (size_t)(ldrow0 + 64) * 8192 + kb + ldc * 16);
        }
    };

    const int g = lane >> 3, r = lane & 7;
    uint32_t offA[2][2], offB[4][2];
    #pragma unroll
    for (int mt = 0; mt < 2; mt++)
        #pragma unroll
        for (int ks = 0; ks < 2; ks++)
            offA[mt][ks] = swz64(wm * 32 + mt * 16 + (g & 1) * 8 + r, ks * 2 + (g >> 1));
    #pragma unroll
    for (int p = 0; p < 4; p++)
        #pragma unroll
        for (int ks = 0; ks < 2; ks++)
            offB[p][ks] = swz64(wn * 64 + p * 16 + (g >> 1) * 8 + r, ks * 2 + (g & 1));

    float acc[2][8][4];
    #pragma unroll
    for (int mt = 0; mt < 2; mt++)
        #pragma unroll
        for (int nt = 0; nt < 8; nt++)
            #pragma unroll
            for (int q = 0; q < 4; q++) acc[mt][nt][q] = 0.f;

    load_stage(0, 0); cp_commit();
    load_stage(1, 1); cp_commit();

    int st = 0;
    for (int i = 0; i < KITERS; i++) {
        cp_wait1();
        __syncthreads();
        int pst = st + 2; if (pst >= 3) pst -= 3;
        if (i + 2 < KITERS) load_stage(pst, i + 2);
        cp_commit();

        uint32_t base = sb + st * STG;
        #pragma unroll
        for (int ks = 0; ks < 2; ks++) {
            uint32_t ah[2][4], al[2][4], bh[8][2], bl[8][2];
            #pragma unroll
            for (int mt = 0; mt < 2; mt++) {
                ldsm4(ah[mt], base + offA[mt][ks]);
                ldsm4(al[mt], base + 8192 + offA[mt][ks]);
            }
            #pragma unroll
            for (int p = 0; p < 4; p++) {
                uint32_t t4[4];
                ldsm4(t4, base + 16384 + offB[p][ks]);
                bh[2*p][0] = t4[0]; bh[2*p][1] = t4[1];
                bh[2*p+1][0] = t4[2]; bh[2*p+1][1] = t4[3];
                ldsm4(t4, base + 24576 + offB[p][ks]);
                bl[2*p][0] = t4[0]; bl[2*p][1] = t4[1];
                bl[2*p+1][0] = t4[2]; bl[2*p+1][1] = t4[3];
            }
            #pragma unroll
            for (int mt = 0; mt < 2; mt++)
                #pragma unroll
                for (int nt = 0; nt < 8; nt++) {
                    mma16816(acc[mt][nt], ah[mt], bh[nt]);
                    mma16816(acc[mt][nt], ah[mt], bl[nt]);
                    mma16816(acc[mt][nt], al[mt], bh[nt]);
                }
        }
        st += 1; if (st >= 3) st -= 3;
    }

    if (mode == 0) {
        #pragma unroll
        for (int mt = 0; mt < 2; mt++) {
            int row0 = m0 + wm * 32 + mt * 16 + (lane >> 2);
            #pragma unroll
            for (int nt = 0; nt < 8; nt++) {
                int col = n0 + wn * 64 + nt * 8 + (lane & 3) * 2;
                float bx = __ldg(bias + col), by = __ldg(bias + col + 1);
                float2 v0 = make_float2(acc[mt][nt][0] + bx, acc[mt][nt][1] + by);
                float2 v1 = make_float2(acc[mt][nt][2] + bx, acc[mt][nt][3] + by);
                *(float2*)&C[(size_t)row0 * N + col] = v0;
                *(float2*)&C[(size_t)(row0 + 8) * N + col] = v1;
            }
        }
        return;
    }

    // ---- mode 1: fused QKV epilogue ----
    const int part  = blockIdx.y >> 5;                 // 0=Q, 1=K, 2=V
    const int hglob = ((n0 & 4095) >> 6) + wn;         // warp's head
    const int dbase = (lane & 3) * 2;

    float bcol[8][2], wln[8][2], bln[8][2];
    #pragma unroll
    for (int nt = 0; nt < 8; nt++)
        #pragma unroll
        for (int j = 0; j < 2; j++) {
            int d = nt * 8 + dbase + j;
            bcol[nt][j] = __ldg(bias + hglob * 192 + part * 64 + d);
            if (part < 2) {
                wln[nt][j] = __ldg((part == 0 ? qw : kw) + d);
                bln[nt][j] = __ldg((part == 0 ? qb : kb) + d);
            }
        }
    __nv_bfloat16* Oh_ = part == 0 ? Qh : (part == 1 ? Kh : Vh);
    __nv_bfloat16* Ol_ = part == 0 ? Ql : (part == 1 ? Kl : Vl);

    #pragma unroll
    for (int mt = 0; mt < 2; mt++)
        #pragma unroll
        for (int ri = 0; ri < 2; ri++) {
            int row = m0 + wm * 32 + mt * 16 + (lane >> 2) + ri * 8;
            float x[8][2];
            #pragma unroll
            for (int nt = 0; nt < 8; nt++) {
                x[nt][0] = acc[mt][nt][2 * ri + 0] + bcol[nt][0];
                x[nt][1] = acc[mt][nt][2 * ri + 1] + bcol[nt][1];
            }
            if (part < 2) {
                float sum = 0.f;
                #pragma unroll
                for (int nt = 0; nt < 8; nt++) sum += x[nt][0] + x[nt][1];
                sum += __shfl_xor_sync(0xffffffffu, sum, 1);
                sum += __shfl_xor_sync(0xffffffffu, sum, 2);
                float mu = sum * (1.f / 64.f);
                float vs = 0.f;
                #pragma unroll
                for (int nt = 0; nt < 8; nt++) {
                    float d0 = x[nt][0] - mu, d1 = x[nt][1] - mu;
                    vs += d0 * d0 + d1 * d1;
                }
                vs += __shfl_xor_sync(0xffffffffu, vs, 1);
                vs += __shfl_xor_sync(0xffffffffu, vs, 2);
                float rstd = rsqrtf(vs * (1.f / 64.f) + EPS);
                #pragma unroll
                for (int nt = 0; nt < 8; nt++) {
                    x[nt][0] = (x[nt][0] - mu) * rstd * wln[nt][0] + bln[nt][0];
                    x[nt][1] = (x[nt][1] - mu) * rstd * wln[nt][1] + bln[nt][1];
                }
                float c_[2][2], s_[2][2];
                #pragma unroll
                for (int a = 0; a < 2; a++)
                    #pragma unroll
                    for (int j = 0; j < 2; j++) {
                        int f = a * 8 + dbase + j;
                        c_[a][j] = __ldg(cosT + row * 16 + f);
                        s_[a][j] = __ldg(sinT + row * 16 + f);
                    }
                float yr[4][2];
                #pragma unroll
                for (int nt = 0; nt < 4; nt++)
                    #pragma unroll
                    for (int j = 0; j < 2; j++) {
                        float sign = nt < 2 ? -1.f : 1.f;
                        yr[nt][j] = x[nt][j] * c_[nt & 1][j] + sign * x[nt ^ 2][j] * s_[nt & 1][j];
                    }
                #pragma unroll
                for (int nt = 0; nt < 4; nt++) { x[nt][0] = yr[nt][0]; x[nt][1] = yr[nt][1]; }
                if (part == 0) {
                    #pragma unroll
                    for (int nt = 0; nt < 8; nt++) { x[nt][0] *= QSCALE; x[nt][1] *= QSCALE; }
                }
            }
            size_t ob = ((size_t)hglob * S + row) * 64 + dbase;
            #pragma unroll
            for (int nt = 0; nt < 8; nt++) {
                __nv_bfloat16 ha = __float2bfloat16(x[nt][0]);
                __nv_bfloat16 hb = __float2bfloat16(x[nt][1]);
                __nv_bfloat162 hp(ha, hb);
                __nv_bfloat162 lp(__float2bfloat16(x[nt][0] - __bfloat162float(ha)),
                                  __float2bfloat16(x[nt][1] - __bfloat162float(hb)));
                *(__nv_bfloat162*)&Oh_[ob + nt * 8] = hp;
                *(__nv_bfloat162*)&Ol_[ob + nt * 8] = lp;
            }
        }
}

// ---------------- flash attention: 128-q tile, 3-stage ring aliasing Q -----
#define ATT_STGSZ 32768
#define ATT_SMEM  (3 * ATT_STGSZ)

__global__ __launch_bounds__(256)
void flash_attn(const __nv_bfloat16* __restrict__ Qh, const __nv_bfloat16* __restrict__ Ql,
                const __nv_bfloat16* __restrict__ Kh, const __nv_bfloat16* __restrict__ Kl,
                const __nv_bfloat16* __restrict__ Vh, const __nv_bfloat16* __restrict__ Vl,
                __nv_bfloat16* __restrict__ Oh, __nv_bfloat16* __restrict__ Ol)
{
    extern __shared__ __align__(128) char smem[];
    const uint32_t sb = smem_u32(smem);
    const int h = blockIdx.y;
    const int t = gridDim.x - 1 - blockIdx.x;
    const int tid = threadIdx.x, warp = tid >> 5, lane = tid & 31;
    const int g = lane >> 3, r = lane & 7;

    const char* qhp = (const char*)(Qh + ((size_t)h * S + t * 128) * HD);
    const char* qlp = (const char*)(Ql + ((size_t)h * S + t * 128) * HD);
    const char* khp = (const char*)(Kh + (size_t)h * S * HD);
    const char* klp = (const char*)(Kl + (size_t)h * S * HD);
    const char* vhp = (const char*)(Vh + (size_t)h * S * HD);
    const char* vlp = (const char*)(Vl + (size_t)h * S * HD);

    const uint32_t regbase[3] = { sb + ATT_STGSZ, sb + 2 * ATT_STGSZ, sb };

    auto load_kv = [&](uint32_t base, int kt) {
        size_t gro = (size_t)kt * 64 * 128;
        for (int i = tid; i < 512; i += 256) {
            int row = i >> 3, c = i & 7;
            uint32_t o = swz128(row, c);
            size_t go = gro + row * 128 + c * 16;
            cp16(base + o,          khp + go);
            cp16(base + 8192 + o,   klp + go);
            cp16(base + 16384 + o,  vhp + go);
            cp16(base + 24576 + o,  vlp + go);
        }
    };

    const int kmax = 2 * t + 1;

    for (int i = tid; i < 1024; i += 256) {
        int row = i >> 3, c = i & 7;
        uint32_t o = swz128(row, c);
        cp16(sb + o, qhp + row * 128 + c * 16);
        cp16(sb + 16384 + o, qlp + row * 128 + c * 16);
    }
    load_kv(regbase[0], 0);
    cp_commit();
    load_kv(regbase[1], 1);
    cp_commit();

    uint32_t aQh[4][4], aQl[4][4];
    uint32_t offA[4];
    #pragma unroll
    for (int kc = 0; kc < 4; kc++)
        offA[kc] = swz128(warp * 16 + (g & 1) * 8 + r, kc * 2 + (g >> 1));

    float accO[8][4];
    #pragma unroll
    for (int nt = 0; nt < 8; nt++)
        #pragma unroll
        for (int c = 0; c < 4; c++) accO[nt][c] = 0.f;
    float m0 = -1e30f, m1 = -1e30f, l0 = 0.f, l1 = 0.f;

    const int qg0   = t * 128 + warp * 16 + (lane >> 2);
    const int qbase = t * 128 + warp * 16;
    const int qmax  = qbase + 15;

    int cur = 0;
    for (int kt = 0; kt <= kmax; kt++) {
        cp_wait1();
        __syncthreads();

        if (kt == 0) {
            #pragma unroll
            for (int kc = 0; kc < 4; kc++) {
                ldsm4(aQh[kc], sb + offA[kc]);
                ldsm4(aQl[kc], sb + 16384 + offA[kc]);
            }
            __syncthreads();
        }

        int pre = cur + 2; if (pre >= 3) pre -= 3;
        if (kt + 2 <= kmax) load_kv(regbase[pre], kt + 2);
        cp_commit();

        uint32_t base = regbase[cur];
        cur += 1; if (cur >= 3) cur -= 3;

        if (kt * 64 > qmax) continue;

        float s[8][4];
        #pragma unroll
        for (int nt = 0; nt < 8; nt++)
            #pragma unroll
            for (int c = 0; c < 4; c++) s[nt][c] = 0.f;
        #pragma unroll
        for (int kc = 0; kc < 4; kc++) {
            #pragma unroll
            for (int p = 0; p < 4; p++) {
                uint32_t offb = swz128(p * 16 + (g >> 1) * 8 + r, kc * 2 + (g & 1));
                uint32_t th[4], tl[4];
                ldsm4(th, base + offb);
                ldsm4(tl, base + 8192 + offb);
                mma16816(s[2*p],   aQh[kc], th);
                mma16816(s[2*p+1], aQh[kc], th + 2);
                mma16816(s[2*p],   aQh[kc], tl);
                mma16816(s[2*p+1], aQh[kc], tl + 2);
                mma16816(s[2*p],   aQl[kc], th);
                mma16816(s[2*p+1], aQl[kc], th + 2);
            }
        }

        if (kt * 64 + 63 > qbase) {
            #pragma unroll
            for (int nt = 0; nt < 8; nt++) {
                int kg = kt * 64 + nt * 8 + (lane & 3) * 2;
                if (kg > qg0)         s[nt][0] = -1e30f;
                if (kg + 1 > qg0)     s[nt][1] = -1e30f;
                if (kg > qg0 + 8)     s[nt][2] = -1e30f;
                if (kg + 1 > qg0 + 8) s[nt][3] = -1e30f;
            }
        }

        float mx0 = -1e30f, mx1 = -1e30f;
        #pragma unroll
        for (int nt = 0; nt < 8; nt++) {
            mx0 = fmaxf(mx0, fmaxf(s[nt][0], s[nt][1]));
            mx1 = fmaxf(mx1, fmaxf(s[nt][2], s[nt][3]));
        }
        mx0 = fmaxf(mx0, __shfl_xor_sync(0xffffffffu, mx0, 1));
        mx0 = fmaxf(mx0, __shfl_xor_sync(0xffffffffu, mx0, 2));
        mx1 = fmaxf(mx1, __shfl_xor_sync(0xffffffffu, mx1, 1));
        mx1 = fmaxf(mx1, __shfl_xor_sync(0xffffffffu, mx1, 2));
        float mn0 = fmaxf(m0, mx0), mn1 = fmaxf(m1, mx1);
        float corr0 = fexp2(m0 - mn0), corr1 = fexp2(m1 - mn1);
        m0 = mn0; m1 = mn1;
        l0 *= corr0; l1 *= corr1;
        #pragma unroll
        for (int nt = 0; nt < 8; nt++) {
            accO[nt][0] *= corr0; accO[nt][1] *= corr0;
            accO[nt][2] *= corr1; accO[nt][3] *= corr1;
        }

        uint32_t Ph0[8], Ph1[8], Pl0[8], Pl1[8];
        #pragma unroll
        for (int nt = 0; nt < 8; nt++) {
            float p0 = fexp2(s[nt][0] - m0);
            float p1 = fexp2(s[nt][1] - m0);
            float p2 = fexp2(s[nt][2] - m1);
            float p3 = fexp2(s[nt][3] - m1);
            l0 += p0 + p1; l1 += p2 + p3;
            __nv_bfloat162 h01 = __floats2bfloat162_rn(p0, p1);
            __nv_bfloat162 h23 = __floats2bfloat162_rn(p2, p3);
            __nv_bfloat162 q01 = __floats2bfloat162_rn(p0 - __low2float(h01), p1 - __high2float(h01));
            __nv_bfloat162 q23 = __floats2bfloat162_rn(p2 - __low2float(h23), p3 - __high2float(h23));
            Ph0[nt] = *(uint32_t*)&h01; Ph1[nt] = *(uint32_t*)&h23;
            Pl0[nt] = *(uint32_t*)&q01; Pl1[nt] = *(uint32_t*)&q23;
        }

        #pragma unroll
        for (int kc = 0; kc < 4; kc++) {
            uint32_t aPh[4] = {Ph0[2*kc], Ph1[2*kc], Ph0[2*kc+1], Ph1[2*kc+1]};
            uint32_t aPl[4] = {Pl0[2*kc], Pl1[2*kc], Pl0[2*kc+1], Pl1[2*kc+1]};
            #pragma unroll
            for (int p = 0; p < 4; p++) {
                uint32_t offv = swz128(kc * 16 + (g & 1) * 8 + r, p * 2 + (g >> 1));
                uint32_t vh[4], vl[4];
                ldsm4t(vh, base + 16384 + offv);
                ldsm4t(vl, base + 24576 + offv);
                mma16816(accO[2*p],   aPh, vh);
                mma16816(accO[2*p+1], aPh, vh + 2);
                mma16816(accO[2*p],   aPh, vl);
                mma16816(accO[2*p+1], aPh, vl + 2);
                mma16816(accO[2*p],   aPl, vh);
                mma16816(accO[2*p+1], aPl, vh + 2);
            }
        }
    }

    l0 += __shfl_xor_sync(0xffffffffu, l0, 1);
    l0 += __shfl_xor_sync(0xffffffffu, l0, 2);
    l1 += __shfl_xor_sync(0xffffffffu, l1, 1);
    l1 += __shfl_xor_sync(0xffffffffu, l1, 2);
    float inv0 = 1.f / l0, inv1 = 1.f / l1;
    int r0 = t * 128 + warp * 16 + (lane >> 2);
    #pragma unroll
    for (int nt = 0; nt < 8; nt++) {
        int col = h * 64 + nt * 8 + (lane & 3) * 2;
        float o0 = accO[nt][0] * inv0, o1 = accO[nt][1] * inv0;
        float o2 = accO[nt][2] * inv1, o3 = accO[nt][3] * inv1;
        __nv_bfloat162 h01 = __floats2bfloat162_rn(o0, o1);
        __nv_bfloat162 h23 = __floats2bfloat162_rn(o2, o3);
        __nv_bfloat162 q01 = __floats2bfloat162_rn(o0 - __low2float(h01), o1 - __high2float(h01));
        __nv_bfloat162 q23 = __floats2bfloat162_rn(o2 - __low2float(h23), o3 - __high2float(h23));
        *(__nv_bfloat162*)&Oh[(size_t)r0 * HID + col] = h01;
        *(__nv_bfloat162*)&Ol[(size_t)r0 * HID + col] = q01;
        *(__nv_bfloat162*)&Oh[(size_t)(r0 + 8) * HID + col] = h23;
        *(__nv_bfloat162*)&Ol[(size_t)(r0 + 8) * HID + col] = q23;
    }
}

// ---------------- launch ---------------------------------------------------
extern "C" void kernel_launch(void* const* d_in, const int* in_sizes, int n_in,
                              void* d_out, int out_size)
{
    const float* hs    = (const float*)d_in[0];
    const float* Wqkv  = (const float*)d_in[3];
    const float* bqkv  = (const float*)d_in[4];
    const float* Wd    = (const float*)d_in[5];
    const float* bd    = (const float*)d_in[6];
    const float* qw    = (const float*)d_in[7];
    const float* qb    = (const float*)d_in[8];
    const float* kw    = (const float*)d_in[9];
    const float* kb    = (const float*)d_in[10];
    float* out = (float*)d_out;

    float *cosT, *sinT;
    __nv_bfloat16 *Ahp, *Alp, *Bqh, *Bql, *Bdh, *Bdl;
    __nv_bfloat16 *Qhp, *Qlp, *Khp, *Klp, *Vhp, *Vlp;
    cudaGetSymbolAddress((void**)&cosT,  g_cos);
    cudaGetSymbolAddress((void**)&sinT,  g_sin);
    cudaGetSymbolAddress((void**)&Ahp,   g_Ah);
    cudaGetSymbolAddress((void**)&Alp,   g_Al);
    cudaGetSymbolAddress((void**)&Bqh,   g_Bqh);
    cudaGetSymbolAddress((void**)&Bql,   g_Bql);
    cudaGetSymbolAddress((void**)&Bdh,   g_Bdh);
    cudaGetSymbolAddress((void**)&Bdl,   g_Bdl);
    cudaGetSymbolAddress((void**)&Qhp,   g_Qh);
    cudaGetSymbolAddress((void**)&Qlp,   g_Ql);
    cudaGetSymbolAddress((void**)&Khp,   g_Kh);
    cudaGetSymbolAddress((void**)&Klp,   g_Kl);
    cudaGetSymbolAddress((void**)&Vhp,   g_Vh);
    cudaGetSymbolAddress((void**)&Vlp,   g_Vl);

    static int attr_set = 0;
    static cudaStream_t s1;
    static cudaEvent_t evFork, evRows, evDense;
    if (!attr_set) {
        cudaFuncSetAttribute(gemm_bf16x3, cudaFuncAttributeMaxDynamicSharedMemorySize, GEMM_SMEM);
        cudaFuncSetAttribute(flash_attn, cudaFuncAttributeMaxDynamicSharedMemorySize, ATT_SMEM);
        cudaStreamCreate(&s1);
        cudaEventCreateWithFlags(&evFork,  cudaEventDisableTiming);
        cudaEventCreateWithFlags(&evRows,  cudaEventDisableTiming);
        cudaEventCreateWithFlags(&evDense, cudaEventDisableTiming);
        attr_set = 1;
    }

    // fork: s1 runs split_rows (needed by GEMM1) then dense transpose (GEMM2)
    cudaEventRecord(evFork, 0);
    cudaStreamWaitEvent(s1, evFork, 0);
    split_rows<<<(S * HID / 4 + 255) / 256, 256, 0, s1>>>(hs, Ahp, Alp, S * HID / 4);
    cudaEventRecord(evRows, s1);
    split_transpose<<<dim3(HID / 32, HID / 128), dim3(32, 8), 0, s1>>>(Wd, Bdh, Bdl, KDIM, HID, 0);
    cudaEventRecord(evDense, s1);

    // main chain
    rope_init<<<(S * 16 + 255) / 256, 256>>>(cosT, sinT);
    split_transpose<<<dim3(QKV3 / 32, HID / 128), dim3(32, 8)>>>(Wqkv, Bqh, Bql, KDIM, QKV3, 1);

    // join split_rows before GEMM1 consumes Ah/Al
    cudaStreamWaitEvent(0, evRows, 0);
    gemm_bf16x3<<<dim3(S / 128, QKV3 / 128), 256, GEMM_SMEM>>>(
        Ahp, Alp, Bqh, Bql, bqkv, nullptr, QKV3, 1,
        qw, qb, kw, kb, cosT, sinT, Qhp, Qlp, Khp, Klp, Vhp, Vlp);

    flash_attn<<<dim3(S / 128, NH), 256, ATT_SMEM>>>(Qhp, Qlp, Khp, Klp, Vhp, Vlp, Ahp, Alp);

    // join dense transpose before GEMM2 consumes Bdh/Bdl
    cudaStreamWaitEvent(0, evDense, 0);
    gemm_bf16x3<<<dim3(S / 128, HID / 128), 256, GEMM_SMEM>>>(
        Ahp, Alp, Bdh, Bdl, bd, out, HID, 0,
        nullptr, nullptr, nullptr, nullptr, nullptr, nullptr,
        nullptr, nullptr, nullptr, nullptr, nullptr, nullptr);
}